// round 14
// baseline (speedup 1.0000x reference)
#include <cuda_runtime.h>
#include <cuda_fp16.h>
#include <math.h>
#include <stdint.h>

// ---------------------------------------------------------------------------
// Problem constants
// ---------------------------------------------------------------------------
#define BB    2
#define QQ    1024
#define HH    32
#define KVH   8
#define HD    64
#define HS    2048
#define K2HS  4096
#define LCK   2
#define SCALE 0.125f

#define NEG_INF (__int_as_float(0xff800000))

// ---------------------------------------------------------------------------
// Scratch (no cudaMalloc allowed)
// ---------------------------------------------------------------------------
__device__ float g_q  [BB * QQ * HH  * HD];
__device__ float g_k  [BB * QQ * KVH * HD];
__device__ float g_v  [BB * QQ * KVH * HD];
__device__ double g_invf[32];

// fp16 operands: A-side split (hi/lo), B-side single
__device__ __half c_hid_h[2048 * 4096];
__device__ __half c_hid_l[2048 * 4096];
__device__ __half c_wq [2048 * 4096];
__device__ __half c_wk [512  * 4096];
__device__ __half c_wv [512  * 4096];
__device__ __half c_wo [2048 * 2048];
__device__ __half c_at_h[2048 * 2048];
__device__ __half c_at_l[2048 * 2048];
__device__ __half c_qh [2048 * 2048];
__device__ __half c_ql [2048 * 2048];
__device__ __half c_k0 [BB * HH * QQ * HD];
__device__ __half c_v0 [BB * HH * QQ * HD];

// ---------------------------------------------------------------------------
// PTX helpers — plain-sm_100 legal only
// ---------------------------------------------------------------------------
__device__ __forceinline__ uint32_t smem_u32(const void* p) {
    uint32_t a;
    asm("{ .reg .u64 t; cvta.to.shared.u64 t, %1; cvt.u32.u64 %0, t; }"
        : "=r"(a) : "l"(p));
    return a;
}

#define CP_ASYNC16(dst, src) \
    asm volatile("cp.async.cg.shared.global [%0], [%1], 16;" \
                 :: "r"((uint32_t)(dst)), "l"(src))
#define CP_COMMIT() asm volatile("cp.async.commit_group;" ::: "memory")
#define CP_WAIT0()  asm volatile("cp.async.wait_group 0;" ::: "memory")
#define CP_WAIT1()  asm volatile("cp.async.wait_group 1;" ::: "memory")

__device__ __forceinline__ void ldsm4(uint32_t* r, uint32_t addr) {
    asm volatile("ldmatrix.sync.aligned.m8n8.x4.shared.b16 {%0,%1,%2,%3}, [%4];"
        : "=r"(r[0]), "=r"(r[1]), "=r"(r[2]), "=r"(r[3]) : "r"(addr));
}
__device__ __forceinline__ void ldsm4t(uint32_t* r, uint32_t addr) {
    asm volatile("ldmatrix.sync.aligned.m8n8.x4.trans.shared.b16 {%0,%1,%2,%3}, [%4];"
        : "=r"(r[0]), "=r"(r[1]), "=r"(r[2]), "=r"(r[3]) : "r"(addr));
}

__device__ __forceinline__ void mma_tc(float* d, const uint32_t* a, const uint32_t* b) {
    asm volatile(
        "mma.sync.aligned.m16n8k16.row.col.f32.f16.f16.f32 "
        "{%0,%1,%2,%3}, {%4,%5,%6,%7}, {%8,%9}, {%0,%1,%2,%3};"
        : "+f"(d[0]), "+f"(d[1]), "+f"(d[2]), "+f"(d[3])
        : "r"(a[0]), "r"(a[1]), "r"(a[2]), "r"(a[3]), "r"(b[0]), "r"(b[1]));
}

__device__ __forceinline__ uint32_t packhf(float hi, float lo) {
    uint32_t r;
    asm("cvt.rn.f16x2.f32 %0, %1, %2;" : "=r"(r) : "f"(hi), "f"(lo));
    return r;
}

// ---------------------------------------------------------------------------
// inv_freq table setup
// ---------------------------------------------------------------------------
__global__ void setup_invf()
{
    int d = threadIdx.x;
    if (d < 32) g_invf[d] = pow(10000.0, -(double)d / 32.0);
}

// ---------------------------------------------------------------------------
// fp32 -> (fp16 hi, fp16 lo) split conversion (hidden, scale=1).
// ---------------------------------------------------------------------------
__global__ void convert_hl16(const float* __restrict__ x, __half* __restrict__ h,
                             __half* __restrict__ l)
{
    int i0 = blockIdx.x * 1024 + threadIdx.x;
    float4 v[4];
    #pragma unroll
    for (int u = 0; u < 4; u++)
        v[u] = ((const float4*)x)[i0 + u * 256];
    #pragma unroll
    for (int u = 0; u < 4; u++) {
        int i = i0 + u * 256;
        __half h0 = __float2half(v[u].x);
        __half h1 = __float2half(v[u].y);
        __half h2 = __float2half(v[u].z);
        __half h3 = __float2half(v[u].w);
        __half2* hp = (__half2*)h + i * 2;
        __half2* lp = (__half2*)l + i * 2;
        hp[0] = __halves2half2(h0, h1);
        hp[1] = __halves2half2(h2, h3);
        lp[0] = __halves2half2(__float2half(v[u].x - __half2float(h0)),
                               __float2half(v[u].y - __half2float(h1)));
        lp[1] = __halves2half2(__float2half(v[u].z - __half2float(h2)),
                               __float2half(v[u].w - __half2float(h3)));
    }
}

// ---------------------------------------------------------------------------
// Batched fp32 -> fp16 single conversion (weights + kv cache): 6 jobs.
// ---------------------------------------------------------------------------
struct BatchJobs {
    const float* x[6];
    __half*      h[6];
    int          start[6];
};

__global__ void convert_batch(BatchJobs jb)
{
    int bid = blockIdx.x;
    int s = 0;
    #pragma unroll
    for (int k = 1; k < 6; k++)
        if (bid >= jb.start[k]) s = k;
    const float4* xp = (const float4*)jb.x[s];
    __half2* hp = (__half2*)jb.h[s];
    int i0 = (bid - jb.start[s]) * 1024 + threadIdx.x;
    float4 v[4];
    #pragma unroll
    for (int u = 0; u < 4; u++)
        v[u] = xp[i0 + u * 256];
    #pragma unroll
    for (int u = 0; u < 4; u++) {
        int i = i0 + u * 256;
        hp[2 * i]     = __halves2half2(__float2half(v[u].x), __float2half(v[u].y));
        hp[2 * i + 1] = __halves2half2(__float2half(v[u].z), __float2half(v[u].w));
    }
}

// ---------------------------------------------------------------------------
// Fused RoPE (+ Q scale + fp16 hi/lo split). k rotated in place (fp32).
// ---------------------------------------------------------------------------
__global__ void rope_conv(float* __restrict__ q, float* __restrict__ k,
                          const int* __restrict__ pos_ids,
                          __half* __restrict__ qh, __half* __restrict__ ql)
{
    const int NQ = BB * QQ * HH  * 32;
    const int NK = BB * QQ * KVH * 32;
    int i = blockIdx.x * blockDim.x + threadIdx.x;
    if (i >= NQ + NK) return;

    const double TWO_PI  = 6.283185307179586476925286766559;
    const double INV_2PI = 0.15915494309189533576888376337251;

    if (i < NQ) {
        int d = i & 31;
        int m = i >> 10;
        size_t off = (size_t)m * (HH * HD) + ((i >> 5) & (HH - 1)) * HD + d;
        double ang = (double)(pos_ids[m] + LCK) * g_invf[d];
        double r = fma(-rint(ang * INV_2PI), TWO_PI, ang);
        float s, c;
        sincosf((float)r, &s, &c);
        float a = q[off], b2 = q[off + 32];
        float r0 = (a * c - b2 * s) * SCALE;
        float r1 = (b2 * c + a * s) * SCALE;
        __half h0 = __float2half(r0);
        __half h1 = __float2half(r1);
        qh[off]      = h0;
        qh[off + 32] = h1;
        ql[off]      = __float2half(r0 - __half2float(h0));
        ql[off + 32] = __float2half(r1 - __half2float(h1));
    } else {
        int j = i - NQ;
        int d = j & 31;
        int m = j >> 8;
        size_t off = (size_t)m * (KVH * HD) + ((j >> 5) & (KVH - 1)) * HD + d;
        double ang = (double)(pos_ids[m] + LCK) * g_invf[d];
        double r = fma(-rint(ang * INV_2PI), TWO_PI, ang);
        float s, c;
        sincosf((float)r, &s, &c);
        float a = k[off], b2 = k[off + 32];
        k[off]      = a  * c - b2 * s;
        k[off + 32] = b2 * c + a  * s;
    }
}

// ---------------------------------------------------------------------------
// 2-product split-fp16 NT GEMM, 64x128 tile, BK=64, 2-stage ring, 3 CTAs/SM.
// Stage = Ah(64x144) + Al(64x144) + B(128x144) = 36864B; 2 stages = 73728B.
// 8 warps: 2 (M) x 4 (N); warp tile 32x32.
// ---------------------------------------------------------------------------
#define ROWB    144
#define A_TILEB (64 * ROWB)              // 9216
#define B_TILEB (128 * ROWB)             // 18432
#define STAGEB  (2 * A_TILEB + B_TILEB)  // 36864
#define GSMEM_BYTES (2 * STAGEB)         // 73728

__device__ __forceinline__ void load_stage(
    uint32_t sb, int buf, const char* Ah, const char* Al, const char* Bh,
    int bm, int bn, int kb, int K, int tid)
{
    uint32_t st = sb + buf * STAGEB;
    #pragma unroll
    for (int j = 0; j < 8; j++) {
        int c   = tid + 256 * j;            // 0..2047
        int seg = c >> 9;                   // 0:Ah 1:Al 2,3:B
        int ch  = c & 7;
        const char* base;
        int row, rb;
        uint32_t dst;
        if (seg == 0)      { base = Ah; rb = bm; row = (c & 511) >> 3;  dst = st + row * ROWB; }
        else if (seg == 1) { base = Al; rb = bm; row = (c & 511) >> 3;  dst = st + A_TILEB + row * ROWB; }
        else               { base = Bh; rb = bn; row = (c - 1024) >> 3; dst = st + 2 * A_TILEB + row * ROWB; }
        CP_ASYNC16(dst + ch * 16,
                   base + ((size_t)(rb + row) * K + kb + ch * 8) * 2);
    }
    CP_COMMIT();
}

__global__ __launch_bounds__(256, 3)
void gemm_tc(const __half* __restrict__ Ah_, const __half* __restrict__ Al_,
             const __half* B0, float* C0, int N0,
             const __half* B1, float* C1, int N1,
             const __half* B2, float* C2, int N2,
             int K)
{
    extern __shared__ __align__(16) char smx[];
    uint32_t sb = smem_u32(smx);
    const int tid  = threadIdx.x;
    const int wid  = tid >> 5;
    const int lane = tid & 31;
    const int wm   = wid >> 2;          // 0..1  (M direction, 32 rows each)
    const int wn   = wid & 3;           // 0..3  (N direction, 32 cols each)
    const int bm   = blockIdx.y * 64;

    int xt = blockIdx.x;
    const __half* Bh; float* C; int ldc, bn;
    int t0 = N0 >> 7, t1 = N1 >> 7;
    if (xt < t0)           { Bh = B0; C = C0; ldc = N0; bn = xt << 7; }
    else if (xt < t0 + t1) { Bh = B1; C = C1; ldc = N1; bn = (xt - t0) << 7; }
    else                   { Bh = B2; C = C2; ldc = N2; bn = (xt - t0 - t1) << 7; }

    const char* cAh = (const char*)Ah_;
    const char* cAl = (const char*)Al_;
    const char* cBh = (const char*)Bh;

    float acc[2][4][4];
    #pragma unroll
    for (int i = 0; i < 2; i++)
        #pragma unroll
        for (int j = 0; j < 4; j++)
            #pragma unroll
            for (int q = 0; q < 4; q++) acc[i][j][q] = 0.f;

    const int nk = K >> 6;
    load_stage(sb, 0, cAh, cAl, cBh, bm, bn, 0,  K, tid);
    load_stage(sb, 1, cAh, cAl, cBh, bm, bn, 64, K, tid);

    const int lr = lane & 15;
    const int lc = lane >> 4;

    for (int t = 0; t < nk; t++) {
        CP_WAIT1();
        __syncthreads();
        uint32_t st = sb + (t & 1) * STAGEB;

        #pragma unroll
        for (int k0 = 0; k0 < 64; k0 += 16) {
            uint32_t ah[2][4], al[2][4], bh[2][4];
            uint32_t ao = (uint32_t)((wm * 32 + lr) * ROWB + (k0 + lc * 8) * 2);
            ldsm4(ah[0], st + ao);
            ldsm4(ah[1], st + ao + 16 * ROWB);
            ldsm4(al[0], st + A_TILEB + ao);
            ldsm4(al[1], st + A_TILEB + ao + 16 * ROWB);
            uint32_t bo = (uint32_t)(2 * A_TILEB + (wn * 32 + lr) * ROWB + (k0 + lc * 8) * 2);
            ldsm4(bh[0], st + bo);
            ldsm4(bh[1], st + bo + 16 * ROWB);
            #pragma unroll
            for (int mt = 0; mt < 2; mt++) {
                #pragma unroll
                for (int nt = 0; nt < 2; nt++) {
                    uint32_t b0[2] = {bh[nt][0], bh[nt][2]};
                    uint32_t b1[2] = {bh[nt][1], bh[nt][3]};
                    mma_tc(acc[mt][2 * nt],     ah[mt], b0);
                    mma_tc(acc[mt][2 * nt],     al[mt], b0);
                    mma_tc(acc[mt][2 * nt + 1], ah[mt], b1);
                    mma_tc(acc[mt][2 * nt + 1], al[mt], b1);
                }
            }
        }
        __syncthreads();
        if (t + 2 < nk)
            load_stage(sb, t & 1, cAh, cAl, cBh, bm, bn, (t + 2) * 64, K, tid);
        else
            CP_COMMIT();
    }

    const int lg = lane >> 2;
    const int lq = lane & 3;
    #pragma unroll
    for (int mt = 0; mt < 2; mt++) {
        int row = bm + wm * 32 + mt * 16 + lg;
        #pragma unroll
        for (int nf = 0; nf < 4; nf++) {
            float* p = C + (size_t)row * ldc + bn + wn * 32 + nf * 8 + 2 * lq;
            *(float2*)p               = make_float2(acc[mt][nf][0], acc[mt][nf][1]);
            *(float2*)(p + 8 * ldc)   = make_float2(acc[mt][nf][2], acc[mt][nf][3]);
        }
    }
}

// ---------------------------------------------------------------------------
// Tensor-core flash attention, 2-product fp16 (round-13 config, LPT order).
// ---------------------------------------------------------------------------
#define BQ    128
#define BKEY  128
#define QROWB 144
#define SM_QH 0
#define SM_QL 18432
#define SM_ST 36864
#define STG_SZ 36864
#define OFF_KH 0
#define OFF_VH 18432
#define ATTN_SMEM2 (SM_ST + 2 * STG_SZ)   // 110592

__device__ __forceinline__ void attn_ldkv(uint32_t sb, int stg,
    const char* kh, const char* vh, size_t base2, int tid)
{
    uint32_t st = sb + SM_ST + stg * STG_SZ;
    #pragma unroll
    for (int j = 0; j < 4; j++) {
        int c = tid + 256 * j;
        int row = c >> 3, ch = c & 7;
        size_t off = base2 + (size_t)row * 128 + ch * 16;
        uint32_t d = row * QROWB + ch * 16;
        CP_ASYNC16(st + OFF_KH + d, kh + off);
        CP_ASYNC16(st + OFF_VH + d, vh + off);
    }
    CP_COMMIT();
}

__global__ __launch_bounds__(256, 1)
void attn_mma(const __half* __restrict__ qh_g, const __half* __restrict__ ql_g,
              const __half* __restrict__ k0, const __half* __restrict__ v0,
              const float* __restrict__ cache_k, const float* __restrict__ cache_v,
              const float* __restrict__ gk, const float* __restrict__ gv,
              __half* __restrict__ outh, __half* __restrict__ outl)
{
    extern __shared__ __align__(16) char smp[];
    uint32_t sb = smem_u32(smp);
    const int tid = threadIdx.x, wid = tid >> 5, lane = tid & 31;
    const int lg = lane >> 2, lq = lane & 3;
    const int qt = (int)gridDim.x - 1 - (int)blockIdx.x;   // LPT
    const int h = blockIdx.y, b = blockIdx.z;
    const int qb = qt * BQ;

    {
        const char* ch_ = (const char*)qh_g;
        const char* cl_ = (const char*)ql_g;
        #pragma unroll
        for (int j = 0; j < 4; j++) {
            int c = tid + 256 * j;
            int row = c >> 3, ch = c & 7;
            size_t off = (((size_t)(b * QQ + qb + row)) * 2048 + h * 64 + ch * 8) * 2;
            uint32_t d = row * QROWB + ch * 16;
            CP_ASYNC16(sb + SM_QH + d, ch_ + off);
            CP_ASYNC16(sb + SM_QL + d, cl_ + off);
        }
        CP_COMMIT();
    }

    const char* ck0 = (const char*)k0;
    const char* cv0 = (const char*)v0;
    size_t kvb2 = ((size_t)(b * HH + h)) * QQ * 64 * 2;
    attn_ldkv(sb, 0, ck0, cv0, kvb2, tid);
    if (qt >= 1)
        attn_ldkv(sb, 1, ck0, cv0, kvb2 + (size_t)BKEY * 128, tid);

    float s[16][4], o[8][4];
    #pragma unroll
    for (int nf = 0; nf < 8; nf++)
        #pragma unroll
        for (int c = 0; c < 4; c++) o[nf][c] = 0.f;
    float mr0 = NEG_INF, mr1 = NEG_INF, lr0 = 0.f, lr1 = 0.f;
    uint32_t qah[4][4], qal[4][4];

    for (int kt = 0; kt <= qt; kt++) {
        if (kt < qt) { CP_WAIT1(); } else { CP_WAIT0(); }
        __syncthreads();
        uint32_t st = sb + SM_ST + (kt & 1) * STG_SZ;

        if (kt == 0) {
            #pragma unroll
            for (int kc = 0; kc < 4; kc++) {
                uint32_t ao = (wid * 16 + (lane & 15)) * QROWB + (kc * 16 + (lane >> 4) * 8) * 2;
                ldsm4(qah[kc], sb + SM_QH + ao);
                ldsm4(qal[kc], sb + SM_QL + ao);
            }
        }

        #pragma unroll
        for (int nf = 0; nf < 16; nf++)
            #pragma unroll
            for (int c = 0; c < 4; c++) s[nf][c] = 0.f;
        #pragma unroll
        for (int kc = 0; kc < 4; kc++) {
            #pragma unroll
            for (int kg = 0; kg < 8; kg++) {
                uint32_t bo = (kg * 16 + (lane & 15)) * QROWB + (kc * 16 + (lane >> 4) * 8) * 2;
                uint32_t bh_[4];
                ldsm4(bh_, st + OFF_KH + bo);
                uint32_t b0[2] = {bh_[0], bh_[2]}, b1[2] = {bh_[1], bh_[3]};
                mma_tc(s[2 * kg],     qah[kc], b0);
                mma_tc(s[2 * kg],     qal[kc], b0);
                mma_tc(s[2 * kg + 1], qah[kc], b1);
                mma_tc(s[2 * kg + 1], qal[kc], b1);
            }
        }

        if (kt == qt) {
            int r0 = wid * 16 + lg;
            #pragma unroll
            for (int nf = 0; nf < 16; nf++) {
                int k0c = nf * 8 + 2 * lq;
                if (k0c     > r0)     s[nf][0] = -1e30f;
                if (k0c + 1 > r0)     s[nf][1] = -1e30f;
                if (k0c     > r0 + 8) s[nf][2] = -1e30f;
                if (k0c + 1 > r0 + 8) s[nf][3] = -1e30f;
            }
        }

        float mx0 = NEG_INF, mx1 = NEG_INF;
        #pragma unroll
        for (int nf = 0; nf < 16; nf++) {
            mx0 = fmaxf(mx0, fmaxf(s[nf][0], s[nf][1]));
            mx1 = fmaxf(mx1, fmaxf(s[nf][2], s[nf][3]));
        }
        mx0 = fmaxf(mx0, __shfl_xor_sync(0xffffffffu, mx0, 1));
        mx0 = fmaxf(mx0, __shfl_xor_sync(0xffffffffu, mx0, 2));
        mx1 = fmaxf(mx1, __shfl_xor_sync(0xffffffffu, mx1, 1));
        mx1 = fmaxf(mx1, __shfl_xor_sync(0xffffffffu, mx1, 2));
        float mn0 = fmaxf(mr0, mx0), mn1 = fmaxf(mr1, mx1);
        float al0 = __expf(mr0 - mn0), al1 = __expf(mr1 - mn1);
        mr0 = mn0; mr1 = mn1;
        float sum0 = 0.f, sum1 = 0.f;
        #pragma unroll
        for (int nf = 0; nf < 16; nf++) {
            s[nf][0] = __expf(s[nf][0] - mn0); sum0 += s[nf][0];
            s[nf][1] = __expf(s[nf][1] - mn0); sum0 += s[nf][1];
            s[nf][2] = __expf(s[nf][2] - mn1); sum1 += s[nf][2];
            s[nf][3] = __expf(s[nf][3] - mn1); sum1 += s[nf][3];
        }
        sum0 += __shfl_xor_sync(0xffffffffu, sum0, 1);
        sum0 += __shfl_xor_sync(0xffffffffu, sum0, 2);
        sum1 += __shfl_xor_sync(0xffffffffu, sum1, 1);
        sum1 += __shfl_xor_sync(0xffffffffu, sum1, 2);
        lr0 = lr0 * al0 + sum0;
        lr1 = lr1 * al1 + sum1;
        #pragma unroll
        for (int nf = 0; nf < 8; nf++) {
            o[nf][0] *= al0; o[nf][1] *= al0; o[nf][2] *= al1; o[nf][3] *= al1;
        }

        #pragma unroll
        for (int kc2 = 0; kc2 < 8; kc2++) {
            uint32_t pah[4], pal[4];
            #pragma unroll
            for (int t2 = 0; t2 < 2; t2++) {
                float* sv = s[2 * kc2 + t2];
                __half h0 = __float2half(sv[0]);
                __half h1 = __float2half(sv[1]);
                __half h2 = __float2half(sv[2]);
                __half h3 = __float2half(sv[3]);
                pah[2 * t2]     = ((uint32_t)__half_as_ushort(h1) << 16) | __half_as_ushort(h0);
                pah[2 * t2 + 1] = ((uint32_t)__half_as_ushort(h3) << 16) | __half_as_ushort(h2);
                pal[2 * t2]     = packhf(sv[1] - __half2float(h1), sv[0] - __half2float(h0));
                pal[2 * t2 + 1] = packhf(sv[3] - __half2float(h3), sv[2] - __half2float(h2));
            }
            #pragma unroll
            for (int dg = 0; dg < 4; dg++) {
                uint32_t vo = (kc2 * 16 + (lane & 15)) * QROWB + dg * 32 + (lane >> 4) * 16;
                uint32_t vh_[4];
                ldsm4t(vh_, st + OFF_VH + vo);
                uint32_t b0[2] = {vh_[0], vh_[1]}, b1[2] = {vh_[2], vh_[3]};
                mma_tc(o[2 * dg],     pah, b0);
                mma_tc(o[2 * dg],     pal, b0);
                mma_tc(o[2 * dg + 1], pah, b1);
                mma_tc(o[2 * dg + 1], pal, b1);
            }
        }
        __syncthreads();
        if (kt + 2 <= qt)
            attn_ldkv(sb, kt & 1, ck0, cv0,
                      kvb2 + (size_t)(kt + 2) * BKEY * 128, tid);
    }

    // ---- two diagonal tail keys per row ----
    #pragma unroll 1
    for (int e = 0; e < 2; e++) {
        const float* tk; const float* tv; int stride;
        if (e == 0) {
            size_t off = (((size_t)BB + b) * HH + h) * QQ * HD + (size_t)qb * HD;
            tk = cache_k + off; tv = cache_v + off; stride = 64;
        } else {
            size_t off = ((size_t)(b * QQ + qb)) * 512 + (h >> 2) * 64;
            tk = gk + off; tv = gv + off; stride = 512;
        }
        #pragma unroll
        for (int half = 0; half < 2; half++) {
            int rl = wid * 16 + lg + half * 8;
            const __half* qhp = (const __half*)(smp + SM_QH + rl * QROWB);
            const __half* qlp = (const __half*)(smp + SM_QL + rl * QROWB);
            float dot = 0.f;
            #pragma unroll
            for (int dd = 0; dd < 16; dd++) {
                int d = lq * 16 + dd;
                float qv = __half2float(qhp[d]) + __half2float(qlp[d]);
                dot += qv * tk[(size_t)rl * stride + d];
            }
            dot += __shfl_xor_sync(0xffffffffu, dot, 1);
            dot += __shfl_xor_sync(0xffffffffu, dot, 2);
            float mo = half ? mr1 : mr0;
            float mn = fmaxf(mo, dot);
            float a = __expf(mo - mn), p = __expf(dot - mn);
            if (half) { mr1 = mn; lr1 = lr1 * a + p; }
            else      { mr0 = mn; lr0 = lr0 * a + p; }
            #pragma unroll
            for (int nf = 0; nf < 8; nf++) {
                int d0 = nf * 8 + 2 * lq;
                float v0_ = tv[(size_t)rl * stride + d0];
                float v1_ = tv[(size_t)rl * stride + d0 + 1];
                o[nf][2 * half]     = o[nf][2 * half]     * a + p * v0_;
                o[nf][2 * half + 1] = o[nf][2 * half + 1] * a + p * v1_;
            }
        }
    }

    float inv0 = 1.f / lr0, inv1 = 1.f / lr1;
    #pragma unroll
    for (int half = 0; half < 2; half++) {
        int qrow = qb + wid * 16 + lg + half * 8;
        float inv = half ? inv1 : inv0;
        size_t base = ((size_t)(b * QQ) + qrow) * 2048 + h * 64;
        #pragma unroll
        for (int nf = 0; nf < 8; nf++) {
            float x0 = o[nf][2 * half] * inv;
            float x1 = o[nf][2 * half + 1] * inv;
            __half h0 = __float2half(x0), h1 = __float2half(x1);
            *(__half2*)(outh + base + nf * 8 + 2 * lq) = __halves2half2(h0, h1);
            *(__half2*)(outl + base + nf * 8 + 2 * lq) =
                __halves2half2(__float2half(x0 - __half2float(h0)),
                               __float2half(x1 - __half2float(h1)));
        }
    }
}

// ---------------------------------------------------------------------------
// Launch
// ---------------------------------------------------------------------------
extern "C" void kernel_launch(void* const* d_in, const int* in_sizes, int n_in,
                              void* d_out, int out_size)
{
    (void)in_sizes; (void)n_in; (void)out_size;

    const float* hidden = (const float*)d_in[0];
    const float* Wq     = (const float*)d_in[1];
    const float* Wk     = (const float*)d_in[2];
    const float* Wv     = (const float*)d_in[3];
    const float* Wo     = (const float*)d_in[4];
    const float* ck     = (const float*)d_in[5];
    const float* cv     = (const float*)d_in[6];
    const int*   pos    = (const int*)d_in[8];
    float* out = (float*)d_out;

    float *gq, *gk, *gv;
    cudaGetSymbolAddress((void**)&gq, g_q);
    cudaGetSymbolAddress((void**)&gk, g_k);
    cudaGetSymbolAddress((void**)&gv, g_v);

    __half *hid_h, *hid_l, *wq, *wk, *wv, *wo, *at_h, *at_l, *qh, *ql, *k0, *v0;
    cudaGetSymbolAddress((void**)&hid_h, c_hid_h);
    cudaGetSymbolAddress((void**)&hid_l, c_hid_l);
    cudaGetSymbolAddress((void**)&wq,    c_wq);
    cudaGetSymbolAddress((void**)&wk,    c_wk);
    cudaGetSymbolAddress((void**)&wv,    c_wv);
    cudaGetSymbolAddress((void**)&wo,    c_wo);
    cudaGetSymbolAddress((void**)&at_h,  c_at_h);
    cudaGetSymbolAddress((void**)&at_l,  c_at_l);
    cudaGetSymbolAddress((void**)&qh,    c_qh);
    cudaGetSymbolAddress((void**)&ql,    c_ql);
    cudaGetSymbolAddress((void**)&k0,    c_k0);
    cudaGetSymbolAddress((void**)&v0,    c_v0);

    cudaFuncSetAttribute(gemm_tc,
                         cudaFuncAttributeMaxDynamicSharedMemorySize, GSMEM_BYTES);
    cudaFuncSetAttribute(attn_mma,
                         cudaFuncAttributeMaxDynamicSharedMemorySize, ATTN_SMEM2);

    const int M = BB * QQ;   // 2048

    setup_invf<<<1, 32>>>();

    // hidden -> fp16 hi/lo split
    convert_hl16<<<2048 * 4096 / 4096, 256>>>(hidden, hid_h, hid_l);

    // weights + kv cache -> single fp16, one batched launch
    {
        BatchJobs jb;
        jb.x[0] = Wq; jb.h[0] = wq;
        jb.x[1] = Wk; jb.h[1] = wk;
        jb.x[2] = Wv; jb.h[2] = wv;
        jb.x[3] = Wo; jb.h[3] = wo;
        jb.x[4] = ck; jb.h[4] = k0;
        jb.x[5] = cv; jb.h[5] = v0;
        jb.start[0] = 0;    jb.start[1] = 2048; jb.start[2] = 2560;
        jb.start[3] = 3072; jb.start[4] = 4096; jb.start[5] = 5120;
        convert_batch<<<6144, 256>>>(jb);
    }

    // fused QKV projection (64-row M tiles: grid 24 x 32)
    gemm_tc<<<dim3(24, M / 64), 256, GSMEM_BYTES>>>(
        hid_h, hid_l,
        wq, gq, HH * HD,
        wk, gk, KVH * HD,
        wv, gv, KVH * HD,
        K2HS);

    // fused RoPE + Q split
    {
        int total = BB * QQ * (HH + KVH) * 32;
        rope_conv<<<(total + 255) / 256, 256>>>(gq, gk, pos, qh, ql);
    }

    attn_mma<<<dim3(QQ / BQ, HH, BB), 256, ATTN_SMEM2>>>(
        qh, ql, k0, v0, ck, cv, gk, gv, at_h, at_l);

    // output projection (grid 16 x 32)
    gemm_tc<<<dim3(16, M / 64), 256, GSMEM_BYTES>>>(
        at_h, at_l,
        wo, out, HS,
        (const __half*)0, (float*)0, 0,
        (const __half*)0, (float*)0, 0,
        HH * HD);
}

// round 15
// speedup vs baseline: 1.0113x; 1.0113x over previous
#include <cuda_runtime.h>
#include <cuda_fp16.h>
#include <math.h>
#include <stdint.h>

// ---------------------------------------------------------------------------
// Problem constants
// ---------------------------------------------------------------------------
#define BB    2
#define QQ    1024
#define HH    32
#define KVH   8
#define HD    64
#define HS    2048
#define K2HS  4096
#define LCK   2
#define SCALE 0.125f

#define NEG_INF (__int_as_float(0xff800000))

// ---------------------------------------------------------------------------
// Scratch (no cudaMalloc allowed)
// ---------------------------------------------------------------------------
__device__ float g_q  [BB * QQ * HH  * HD];
__device__ float g_k  [BB * QQ * KVH * HD];
__device__ float g_v  [BB * QQ * KVH * HD];
__device__ double g_invf[32];

// fp16 operands: A-side split (hi/lo), B-side single
__device__ __half c_hid_h[2048 * 4096];
__device__ __half c_hid_l[2048 * 4096];
__device__ __half c_wq [2048 * 4096];
__device__ __half c_wk [512  * 4096];
__device__ __half c_wv [512  * 4096];
__device__ __half c_wo [2048 * 2048];
__device__ __half c_at_h[2048 * 2048];
__device__ __half c_at_l[2048 * 2048];
__device__ __half c_qh [2048 * 2048];
__device__ __half c_ql [2048 * 2048];
__device__ __half c_k0 [BB * HH * QQ * HD];
__device__ __half c_v0 [BB * HH * QQ * HD];

// ---------------------------------------------------------------------------
// PTX helpers — plain-sm_100 legal only
// ---------------------------------------------------------------------------
__device__ __forceinline__ uint32_t smem_u32(const void* p) {
    uint32_t a;
    asm("{ .reg .u64 t; cvta.to.shared.u64 t, %1; cvt.u32.u64 %0, t; }"
        : "=r"(a) : "l"(p));
    return a;
}

#define CP_ASYNC16(dst, src) \
    asm volatile("cp.async.cg.shared.global [%0], [%1], 16;" \
                 :: "r"((uint32_t)(dst)), "l"(src))
#define CP_COMMIT() asm volatile("cp.async.commit_group;" ::: "memory")
#define CP_WAIT0()  asm volatile("cp.async.wait_group 0;" ::: "memory")
#define CP_WAIT1()  asm volatile("cp.async.wait_group 1;" ::: "memory")

__device__ __forceinline__ void ldsm4(uint32_t* r, uint32_t addr) {
    asm volatile("ldmatrix.sync.aligned.m8n8.x4.shared.b16 {%0,%1,%2,%3}, [%4];"
        : "=r"(r[0]), "=r"(r[1]), "=r"(r[2]), "=r"(r[3]) : "r"(addr));
}
__device__ __forceinline__ void ldsm4t(uint32_t* r, uint32_t addr) {
    asm volatile("ldmatrix.sync.aligned.m8n8.x4.trans.shared.b16 {%0,%1,%2,%3}, [%4];"
        : "=r"(r[0]), "=r"(r[1]), "=r"(r[2]), "=r"(r[3]) : "r"(addr));
}

__device__ __forceinline__ void mma_tc(float* d, const uint32_t* a, const uint32_t* b) {
    asm volatile(
        "mma.sync.aligned.m16n8k16.row.col.f32.f16.f16.f32 "
        "{%0,%1,%2,%3}, {%4,%5,%6,%7}, {%8,%9}, {%0,%1,%2,%3};"
        : "+f"(d[0]), "+f"(d[1]), "+f"(d[2]), "+f"(d[3])
        : "r"(a[0]), "r"(a[1]), "r"(a[2]), "r"(a[3]), "r"(b[0]), "r"(b[1]));
}

__device__ __forceinline__ uint32_t packhf(float hi, float lo) {
    uint32_t r;
    asm("cvt.rn.f16x2.f32 %0, %1, %2;" : "=r"(r) : "f"(hi), "f"(lo));
    return r;
}

// ---------------------------------------------------------------------------
// inv_freq table setup
// ---------------------------------------------------------------------------
__global__ void setup_invf()
{
    int d = threadIdx.x;
    if (d < 32) g_invf[d] = pow(10000.0, -(double)d / 32.0);
}

// ---------------------------------------------------------------------------
// fp32 -> (fp16 hi, fp16 lo) split conversion (hidden, scale=1).
// ---------------------------------------------------------------------------
__global__ void convert_hl16(const float* __restrict__ x, __half* __restrict__ h,
                             __half* __restrict__ l)
{
    int i0 = blockIdx.x * 1024 + threadIdx.x;
    float4 v[4];
    #pragma unroll
    for (int u = 0; u < 4; u++)
        v[u] = ((const float4*)x)[i0 + u * 256];
    #pragma unroll
    for (int u = 0; u < 4; u++) {
        int i = i0 + u * 256;
        __half h0 = __float2half(v[u].x);
        __half h1 = __float2half(v[u].y);
        __half h2 = __float2half(v[u].z);
        __half h3 = __float2half(v[u].w);
        __half2* hp = (__half2*)h + i * 2;
        __half2* lp = (__half2*)l + i * 2;
        hp[0] = __halves2half2(h0, h1);
        hp[1] = __halves2half2(h2, h3);
        lp[0] = __halves2half2(__float2half(v[u].x - __half2float(h0)),
                               __float2half(v[u].y - __half2float(h1)));
        lp[1] = __halves2half2(__float2half(v[u].z - __half2float(h2)),
                               __float2half(v[u].w - __half2float(h3)));
    }
}

// ---------------------------------------------------------------------------
// Batched fp32 -> fp16 single conversion (weights + kv cache): 6 jobs.
// ---------------------------------------------------------------------------
struct BatchJobs {
    const float* x[6];
    __half*      h[6];
    int          start[6];
};

__global__ void convert_batch(BatchJobs jb)
{
    int bid = blockIdx.x;
    int s = 0;
    #pragma unroll
    for (int k = 1; k < 6; k++)
        if (bid >= jb.start[k]) s = k;
    const float4* xp = (const float4*)jb.x[s];
    __half2* hp = (__half2*)jb.h[s];
    int i0 = (bid - jb.start[s]) * 1024 + threadIdx.x;
    float4 v[4];
    #pragma unroll
    for (int u = 0; u < 4; u++)
        v[u] = xp[i0 + u * 256];
    #pragma unroll
    for (int u = 0; u < 4; u++) {
        int i = i0 + u * 256;
        hp[2 * i]     = __halves2half2(__float2half(v[u].x), __float2half(v[u].y));
        hp[2 * i + 1] = __halves2half2(__float2half(v[u].z), __float2half(v[u].w));
    }
}

// ---------------------------------------------------------------------------
// Fused RoPE (+ Q scale + fp16 hi/lo split). k rotated in place (fp32).
// ---------------------------------------------------------------------------
__global__ void rope_conv(float* __restrict__ q, float* __restrict__ k,
                          const int* __restrict__ pos_ids,
                          __half* __restrict__ qh, __half* __restrict__ ql)
{
    const int NQ = BB * QQ * HH  * 32;
    const int NK = BB * QQ * KVH * 32;
    int i = blockIdx.x * blockDim.x + threadIdx.x;
    if (i >= NQ + NK) return;

    const double TWO_PI  = 6.283185307179586476925286766559;
    const double INV_2PI = 0.15915494309189533576888376337251;

    if (i < NQ) {
        int d = i & 31;
        int m = i >> 10;
        size_t off = (size_t)m * (HH * HD) + ((i >> 5) & (HH - 1)) * HD + d;
        double ang = (double)(pos_ids[m] + LCK) * g_invf[d];
        double r = fma(-rint(ang * INV_2PI), TWO_PI, ang);
        float s, c;
        sincosf((float)r, &s, &c);
        float a = q[off], b2 = q[off + 32];
        float r0 = (a * c - b2 * s) * SCALE;
        float r1 = (b2 * c + a * s) * SCALE;
        __half h0 = __float2half(r0);
        __half h1 = __float2half(r1);
        qh[off]      = h0;
        qh[off + 32] = h1;
        ql[off]      = __float2half(r0 - __half2float(h0));
        ql[off + 32] = __float2half(r1 - __half2float(h1));
    } else {
        int j = i - NQ;
        int d = j & 31;
        int m = j >> 8;
        size_t off = (size_t)m * (KVH * HD) + ((j >> 5) & (KVH - 1)) * HD + d;
        double ang = (double)(pos_ids[m] + LCK) * g_invf[d];
        double r = fma(-rint(ang * INV_2PI), TWO_PI, ang);
        float s, c;
        sincosf((float)r, &s, &c);
        float a = k[off], b2 = k[off + 32];
        k[off]      = a  * c - b2 * s;
        k[off + 32] = b2 * c + a  * s;
    }
}

// ---------------------------------------------------------------------------
// 2-product split-fp16 NT GEMM — round-13 structure (128x128, BK=64, 2-stage,
// 2 CTAs/SM); MMA order product-separated: all hi-products, then all
// lo-products (same-acc RAW distance 1 -> 8).
// ---------------------------------------------------------------------------
#define ROWB   144
#define TILEB  (128 * ROWB)          // 18432
#define STAGEB (3 * TILEB)           // 55296
#define GSMEM_BYTES (2 * STAGEB)     // 110592

__device__ __forceinline__ void load_stage(
    uint32_t sb, int buf, const char* Ah, const char* Al, const char* Bh,
    int bm, int bn, int kb, int K, int tid)
{
    uint32_t st = sb + buf * STAGEB;
    #pragma unroll
    for (int j = 0; j < 12; j++) {
        int c    = tid + 256 * j;           // 0..3071
        int tile = c >> 10;                 // 0..2
        int row  = (c >> 3) & 127;
        int ch   = c & 7;
        const char* base = (tile == 0) ? Ah : (tile == 1) ? Al : Bh;
        int rb = (tile < 2) ? bm : bn;
        uint32_t sa = st + tile * TILEB + row * ROWB + ch * 16;
        const char* ga = base + ((size_t)(rb + row) * K + kb + ch * 8) * 2;
        CP_ASYNC16(sa, ga);
    }
    CP_COMMIT();
}

__global__ __launch_bounds__(256, 2)
void gemm_tc(const __half* __restrict__ Ah_, const __half* __restrict__ Al_,
             const __half* B0, float* C0, int N0,
             const __half* B1, float* C1, int N1,
             const __half* B2, float* C2, int N2,
             int K)
{
    extern __shared__ __align__(16) char smx[];
    uint32_t sb = smem_u32(smx);
    const int tid  = threadIdx.x;
    const int wid  = tid >> 5;
    const int lane = tid & 31;
    const int wm   = wid >> 1;
    const int wn   = wid & 1;
    const int bm   = blockIdx.y * 128;

    int xt = blockIdx.x;
    const __half* Bh; float* C; int ldc, bn;
    int t0 = N0 >> 7, t1 = N1 >> 7;
    if (xt < t0)           { Bh = B0; C = C0; ldc = N0; bn = xt << 7; }
    else if (xt < t0 + t1) { Bh = B1; C = C1; ldc = N1; bn = (xt - t0) << 7; }
    else                   { Bh = B2; C = C2; ldc = N2; bn = (xt - t0 - t1) << 7; }

    const char* cAh = (const char*)Ah_;
    const char* cAl = (const char*)Al_;
    const char* cBh = (const char*)Bh;

    float acc[2][8][4];
    #pragma unroll
    for (int i = 0; i < 2; i++)
        #pragma unroll
        for (int j = 0; j < 8; j++)
            #pragma unroll
            for (int q = 0; q < 4; q++) acc[i][j][q] = 0.f;

    const int nk = K >> 6;
    load_stage(sb, 0, cAh, cAl, cBh, bm, bn, 0,  K, tid);
    load_stage(sb, 1, cAh, cAl, cBh, bm, bn, 64, K, tid);

    const int lr = lane & 15;
    const int lc = lane >> 4;

    for (int t = 0; t < nk; t++) {
        CP_WAIT1();
        __syncthreads();
        uint32_t st = sb + (t & 1) * STAGEB;

        #pragma unroll
        for (int k0 = 0; k0 < 64; k0 += 16) {
            uint32_t ah[2][4], al[2][4], bh[4][4];
            uint32_t ao = (uint32_t)((wm * 32 + lr) * ROWB + (k0 + lc * 8) * 2);
            ldsm4(ah[0], st + ao);
            ldsm4(ah[1], st + ao + 16 * ROWB);
            ldsm4(al[0], st + TILEB + ao);
            ldsm4(al[1], st + TILEB + ao + 16 * ROWB);
            uint32_t bo = (uint32_t)((wn * 64 + lr) * ROWB + (k0 + lc * 8) * 2);
            #pragma unroll
            for (int nt = 0; nt < 4; nt++)
                ldsm4(bh[nt], st + 2 * TILEB + bo + nt * 16 * ROWB);
            // hi products for all 16 acc sites (RAW distance >= 8)
            #pragma unroll
            for (int mt = 0; mt < 2; mt++) {
                #pragma unroll
                for (int nt = 0; nt < 4; nt++) {
                    uint32_t b0[2] = {bh[nt][0], bh[nt][2]};
                    uint32_t b1[2] = {bh[nt][1], bh[nt][3]};
                    mma_tc(acc[mt][2 * nt],     ah[mt], b0);
                    mma_tc(acc[mt][2 * nt + 1], ah[mt], b1);
                }
            }
            // lo products for all 16 acc sites
            #pragma unroll
            for (int mt = 0; mt < 2; mt++) {
                #pragma unroll
                for (int nt = 0; nt < 4; nt++) {
                    uint32_t b0[2] = {bh[nt][0], bh[nt][2]};
                    uint32_t b1[2] = {bh[nt][1], bh[nt][3]};
                    mma_tc(acc[mt][2 * nt],     al[mt], b0);
                    mma_tc(acc[mt][2 * nt + 1], al[mt], b1);
                }
            }
        }
        __syncthreads();
        if (t + 2 < nk)
            load_stage(sb, t & 1, cAh, cAl, cBh, bm, bn, (t + 2) * 64, K, tid);
        else
            CP_COMMIT();
    }

    const int lg = lane >> 2;
    const int lq = lane & 3;
    #pragma unroll
    for (int mt = 0; mt < 2; mt++) {
        int row = bm + wm * 32 + mt * 16 + lg;
        #pragma unroll
        for (int nf = 0; nf < 8; nf++) {
            float* p = C + (size_t)row * ldc + bn + wn * 64 + nf * 8 + 2 * lq;
            *(float2*)p               = make_float2(acc[mt][nf][0], acc[mt][nf][1]);
            *(float2*)(p + 8 * ldc)   = make_float2(acc[mt][nf][2], acc[mt][nf][3]);
        }
    }
}

// ---------------------------------------------------------------------------
// Tensor-core flash attention, 2-product fp16; MMA order product-separated.
// ---------------------------------------------------------------------------
#define BQ    128
#define BKEY  128
#define QROWB 144
#define SM_QH 0
#define SM_QL 18432
#define SM_ST 36864
#define STG_SZ 36864
#define OFF_KH 0
#define OFF_VH 18432
#define ATTN_SMEM2 (SM_ST + 2 * STG_SZ)   // 110592

__device__ __forceinline__ void attn_ldkv(uint32_t sb, int stg,
    const char* kh, const char* vh, size_t base2, int tid)
{
    uint32_t st = sb + SM_ST + stg * STG_SZ;
    #pragma unroll
    for (int j = 0; j < 4; j++) {
        int c = tid + 256 * j;
        int row = c >> 3, ch = c & 7;
        size_t off = base2 + (size_t)row * 128 + ch * 16;
        uint32_t d = row * QROWB + ch * 16;
        CP_ASYNC16(st + OFF_KH + d, kh + off);
        CP_ASYNC16(st + OFF_VH + d, vh + off);
    }
    CP_COMMIT();
}

__global__ __launch_bounds__(256, 1)
void attn_mma(const __half* __restrict__ qh_g, const __half* __restrict__ ql_g,
              const __half* __restrict__ k0, const __half* __restrict__ v0,
              const float* __restrict__ cache_k, const float* __restrict__ cache_v,
              const float* __restrict__ gk, const float* __restrict__ gv,
              __half* __restrict__ outh, __half* __restrict__ outl)
{
    extern __shared__ __align__(16) char smp[];
    uint32_t sb = smem_u32(smp);
    const int tid = threadIdx.x, wid = tid >> 5, lane = tid & 31;
    const int lg = lane >> 2, lq = lane & 3;
    const int qt = (int)gridDim.x - 1 - (int)blockIdx.x;   // LPT
    const int h = blockIdx.y, b = blockIdx.z;
    const int qb = qt * BQ;

    {
        const char* ch_ = (const char*)qh_g;
        const char* cl_ = (const char*)ql_g;
        #pragma unroll
        for (int j = 0; j < 4; j++) {
            int c = tid + 256 * j;
            int row = c >> 3, ch = c & 7;
            size_t off = (((size_t)(b * QQ + qb + row)) * 2048 + h * 64 + ch * 8) * 2;
            uint32_t d = row * QROWB + ch * 16;
            CP_ASYNC16(sb + SM_QH + d, ch_ + off);
            CP_ASYNC16(sb + SM_QL + d, cl_ + off);
        }
        CP_COMMIT();
    }

    const char* ck0 = (const char*)k0;
    const char* cv0 = (const char*)v0;
    size_t kvb2 = ((size_t)(b * HH + h)) * QQ * 64 * 2;
    attn_ldkv(sb, 0, ck0, cv0, kvb2, tid);
    if (qt >= 1)
        attn_ldkv(sb, 1, ck0, cv0, kvb2 + (size_t)BKEY * 128, tid);

    float s[16][4], o[8][4];
    #pragma unroll
    for (int nf = 0; nf < 8; nf++)
        #pragma unroll
        for (int c = 0; c < 4; c++) o[nf][c] = 0.f;
    float mr0 = NEG_INF, mr1 = NEG_INF, lr0 = 0.f, lr1 = 0.f;
    uint32_t qah[4][4], qal[4][4];

    for (int kt = 0; kt <= qt; kt++) {
        if (kt < qt) { CP_WAIT1(); } else { CP_WAIT0(); }
        __syncthreads();
        uint32_t st = sb + SM_ST + (kt & 1) * STG_SZ;

        if (kt == 0) {
            #pragma unroll
            for (int kc = 0; kc < 4; kc++) {
                uint32_t ao = (wid * 16 + (lane & 15)) * QROWB + (kc * 16 + (lane >> 4) * 8) * 2;
                ldsm4(qah[kc], sb + SM_QH + ao);
                ldsm4(qal[kc], sb + SM_QL + ao);
            }
        }

        #pragma unroll
        for (int nf = 0; nf < 16; nf++)
            #pragma unroll
            for (int c = 0; c < 4; c++) s[nf][c] = 0.f;
        #pragma unroll
        for (int kc = 0; kc < 4; kc++) {
            #pragma unroll
            for (int kg = 0; kg < 8; kg++) {
                uint32_t bo = (kg * 16 + (lane & 15)) * QROWB + (kc * 16 + (lane >> 4) * 8) * 2;
                uint32_t bh_[4];
                ldsm4(bh_, st + OFF_KH + bo);
                uint32_t b0[2] = {bh_[0], bh_[2]}, b1[2] = {bh_[1], bh_[3]};
                mma_tc(s[2 * kg],     qah[kc], b0);
                mma_tc(s[2 * kg + 1], qah[kc], b1);
                mma_tc(s[2 * kg],     qal[kc], b0);
                mma_tc(s[2 * kg + 1], qal[kc], b1);
            }
        }

        if (kt == qt) {
            int r0 = wid * 16 + lg;
            #pragma unroll
            for (int nf = 0; nf < 16; nf++) {
                int k0c = nf * 8 + 2 * lq;
                if (k0c     > r0)     s[nf][0] = -1e30f;
                if (k0c + 1 > r0)     s[nf][1] = -1e30f;
                if (k0c     > r0 + 8) s[nf][2] = -1e30f;
                if (k0c + 1 > r0 + 8) s[nf][3] = -1e30f;
            }
        }

        float mx0 = NEG_INF, mx1 = NEG_INF;
        #pragma unroll
        for (int nf = 0; nf < 16; nf++) {
            mx0 = fmaxf(mx0, fmaxf(s[nf][0], s[nf][1]));
            mx1 = fmaxf(mx1, fmaxf(s[nf][2], s[nf][3]));
        }
        mx0 = fmaxf(mx0, __shfl_xor_sync(0xffffffffu, mx0, 1));
        mx0 = fmaxf(mx0, __shfl_xor_sync(0xffffffffu, mx0, 2));
        mx1 = fmaxf(mx1, __shfl_xor_sync(0xffffffffu, mx1, 1));
        mx1 = fmaxf(mx1, __shfl_xor_sync(0xffffffffu, mx1, 2));
        float mn0 = fmaxf(mr0, mx0), mn1 = fmaxf(mr1, mx1);
        float al0 = __expf(mr0 - mn0), al1 = __expf(mr1 - mn1);
        mr0 = mn0; mr1 = mn1;
        float sum0 = 0.f, sum1 = 0.f;
        #pragma unroll
        for (int nf = 0; nf < 16; nf++) {
            s[nf][0] = __expf(s[nf][0] - mn0); sum0 += s[nf][0];
            s[nf][1] = __expf(s[nf][1] - mn0); sum0 += s[nf][1];
            s[nf][2] = __expf(s[nf][2] - mn1); sum1 += s[nf][2];
            s[nf][3] = __expf(s[nf][3] - mn1); sum1 += s[nf][3];
        }
        sum0 += __shfl_xor_sync(0xffffffffu, sum0, 1);
        sum0 += __shfl_xor_sync(0xffffffffu, sum0, 2);
        sum1 += __shfl_xor_sync(0xffffffffu, sum1, 1);
        sum1 += __shfl_xor_sync(0xffffffffu, sum1, 2);
        lr0 = lr0 * al0 + sum0;
        lr1 = lr1 * al1 + sum1;
        #pragma unroll
        for (int nf = 0; nf < 8; nf++) {
            o[nf][0] *= al0; o[nf][1] *= al0; o[nf][2] *= al1; o[nf][3] *= al1;
        }

        #pragma unroll
        for (int kc2 = 0; kc2 < 8; kc2++) {
            uint32_t pah[4], pal[4];
            #pragma unroll
            for (int t2 = 0; t2 < 2; t2++) {
                float* sv = s[2 * kc2 + t2];
                __half h0 = __float2half(sv[0]);
                __half h1 = __float2half(sv[1]);
                __half h2 = __float2half(sv[2]);
                __half h3 = __float2half(sv[3]);
                pah[2 * t2]     = ((uint32_t)__half_as_ushort(h1) << 16) | __half_as_ushort(h0);
                pah[2 * t2 + 1] = ((uint32_t)__half_as_ushort(h3) << 16) | __half_as_ushort(h2);
                pal[2 * t2]     = packhf(sv[1] - __half2float(h1), sv[0] - __half2float(h0));
                pal[2 * t2 + 1] = packhf(sv[3] - __half2float(h3), sv[2] - __half2float(h2));
            }
            #pragma unroll
            for (int dg = 0; dg < 4; dg++) {
                uint32_t vo = (kc2 * 16 + (lane & 15)) * QROWB + dg * 32 + (lane >> 4) * 16;
                uint32_t vh_[4];
                ldsm4t(vh_, st + OFF_VH + vo);
                uint32_t b0[2] = {vh_[0], vh_[1]}, b1[2] = {vh_[2], vh_[3]};
                mma_tc(o[2 * dg],     pah, b0);
                mma_tc(o[2 * dg + 1], pah, b1);
                mma_tc(o[2 * dg],     pal, b0);
                mma_tc(o[2 * dg + 1], pal, b1);
            }
        }
        __syncthreads();
        if (kt + 2 <= qt)
            attn_ldkv(sb, kt & 1, ck0, cv0,
                      kvb2 + (size_t)(kt + 2) * BKEY * 128, tid);
    }

    // ---- two diagonal tail keys per row ----
    #pragma unroll 1
    for (int e = 0; e < 2; e++) {
        const float* tk; const float* tv; int stride;
        if (e == 0) {
            size_t off = (((size_t)BB + b) * HH + h) * QQ * HD + (size_t)qb * HD;
            tk = cache_k + off; tv = cache_v + off; stride = 64;
        } else {
            size_t off = ((size_t)(b * QQ + qb)) * 512 + (h >> 2) * 64;
            tk = gk + off; tv = gv + off; stride = 512;
        }
        #pragma unroll
        for (int half = 0; half < 2; half++) {
            int rl = wid * 16 + lg + half * 8;
            const __half* qhp = (const __half*)(smp + SM_QH + rl * QROWB);
            const __half* qlp = (const __half*)(smp + SM_QL + rl * QROWB);
            float dot = 0.f;
            #pragma unroll
            for (int dd = 0; dd < 16; dd++) {
                int d = lq * 16 + dd;
                float qv = __half2float(qhp[d]) + __half2float(qlp[d]);
                dot += qv * tk[(size_t)rl * stride + d];
            }
            dot += __shfl_xor_sync(0xffffffffu, dot, 1);
            dot += __shfl_xor_sync(0xffffffffu, dot, 2);
            float mo = half ? mr1 : mr0;
            float mn = fmaxf(mo, dot);
            float a = __expf(mo - mn), p = __expf(dot - mn);
            if (half) { mr1 = mn; lr1 = lr1 * a + p; }
            else      { mr0 = mn; lr0 = lr0 * a + p; }
            #pragma unroll
            for (int nf = 0; nf < 8; nf++) {
                int d0 = nf * 8 + 2 * lq;
                float v0_ = tv[(size_t)rl * stride + d0];
                float v1_ = tv[(size_t)rl * stride + d0 + 1];
                o[nf][2 * half]     = o[nf][2 * half]     * a + p * v0_;
                o[nf][2 * half + 1] = o[nf][2 * half + 1] * a + p * v1_;
            }
        }
    }

    float inv0 = 1.f / lr0, inv1 = 1.f / lr1;
    #pragma unroll
    for (int half = 0; half < 2; half++) {
        int qrow = qb + wid * 16 + lg + half * 8;
        float inv = half ? inv1 : inv0;
        size_t base = ((size_t)(b * QQ) + qrow) * 2048 + h * 64;
        #pragma unroll
        for (int nf = 0; nf < 8; nf++) {
            float x0 = o[nf][2 * half] * inv;
            float x1 = o[nf][2 * half + 1] * inv;
            __half h0 = __float2half(x0), h1 = __float2half(x1);
            *(__half2*)(outh + base + nf * 8 + 2 * lq) = __halves2half2(h0, h1);
            *(__half2*)(outl + base + nf * 8 + 2 * lq) =
                __halves2half2(__float2half(x0 - __half2float(h0)),
                               __float2half(x1 - __half2float(h1)));
        }
    }
}

// ---------------------------------------------------------------------------
// Launch
// ---------------------------------------------------------------------------
extern "C" void kernel_launch(void* const* d_in, const int* in_sizes, int n_in,
                              void* d_out, int out_size)
{
    (void)in_sizes; (void)n_in; (void)out_size;

    const float* hidden = (const float*)d_in[0];
    const float* Wq     = (const float*)d_in[1];
    const float* Wk     = (const float*)d_in[2];
    const float* Wv     = (const float*)d_in[3];
    const float* Wo     = (const float*)d_in[4];
    const float* ck     = (const float*)d_in[5];
    const float* cv     = (const float*)d_in[6];
    const int*   pos    = (const int*)d_in[8];
    float* out = (float*)d_out;

    float *gq, *gk, *gv;
    cudaGetSymbolAddress((void**)&gq, g_q);
    cudaGetSymbolAddress((void**)&gk, g_k);
    cudaGetSymbolAddress((void**)&gv, g_v);

    __half *hid_h, *hid_l, *wq, *wk, *wv, *wo, *at_h, *at_l, *qh, *ql, *k0, *v0;
    cudaGetSymbolAddress((void**)&hid_h, c_hid_h);
    cudaGetSymbolAddress((void**)&hid_l, c_hid_l);
    cudaGetSymbolAddress((void**)&wq,    c_wq);
    cudaGetSymbolAddress((void**)&wk,    c_wk);
    cudaGetSymbolAddress((void**)&wv,    c_wv);
    cudaGetSymbolAddress((void**)&wo,    c_wo);
    cudaGetSymbolAddress((void**)&at_h,  c_at_h);
    cudaGetSymbolAddress((void**)&at_l,  c_at_l);
    cudaGetSymbolAddress((void**)&qh,    c_qh);
    cudaGetSymbolAddress((void**)&ql,    c_ql);
    cudaGetSymbolAddress((void**)&k0,    c_k0);
    cudaGetSymbolAddress((void**)&v0,    c_v0);

    cudaFuncSetAttribute(gemm_tc,
                         cudaFuncAttributeMaxDynamicSharedMemorySize, GSMEM_BYTES);
    cudaFuncSetAttribute(attn_mma,
                         cudaFuncAttributeMaxDynamicSharedMemorySize, ATTN_SMEM2);

    const int M = BB * QQ;   // 2048

    setup_invf<<<1, 32>>>();

    // hidden -> fp16 hi/lo split
    convert_hl16<<<2048 * 4096 / 4096, 256>>>(hidden, hid_h, hid_l);

    // weights + kv cache -> single fp16, one batched launch
    {
        BatchJobs jb;
        jb.x[0] = Wq; jb.h[0] = wq;
        jb.x[1] = Wk; jb.h[1] = wk;
        jb.x[2] = Wv; jb.h[2] = wv;
        jb.x[3] = Wo; jb.h[3] = wo;
        jb.x[4] = ck; jb.h[4] = k0;
        jb.x[5] = cv; jb.h[5] = v0;
        jb.start[0] = 0;    jb.start[1] = 2048; jb.start[2] = 2560;
        jb.start[3] = 3072; jb.start[4] = 4096; jb.start[5] = 5120;
        convert_batch<<<6144, 256>>>(jb);
    }

    // fused QKV projection (A = hidden split, B = weights single)
    gemm_tc<<<dim3(24, M / 128), 256, GSMEM_BYTES>>>(
        hid_h, hid_l,
        wq, gq, HH * HD,
        wk, gk, KVH * HD,
        wv, gv, KVH * HD,
        K2HS);

    // fused RoPE + Q split
    {
        int total = BB * QQ * (HH + KVH) * 32;
        rope_conv<<<(total + 255) / 256, 256>>>(gq, gk, pos, qh, ql);
    }

    attn_mma<<<dim3(QQ / BQ, HH, BB), 256, ATTN_SMEM2>>>(
        qh, ql, k0, v0, ck, cv, gk, gv, at_h, at_l);

    // output projection (A = attention out split, B = Wo single)
    gemm_tc<<<dim3(16, M / 128), 256, GSMEM_BYTES>>>(
        at_h, at_l,
        wo, out, HS,
        (const __half*)0, (float*)0, 0,
        (const __half*)0, (float*)0, 0,
        HH * HD);
}

// round 16
// speedup vs baseline: 1.6500x; 1.6316x over previous
#include <cuda_runtime.h>
#include <cuda_fp16.h>
#include <math.h>
#include <stdint.h>

// ---------------------------------------------------------------------------
// Problem constants
// ---------------------------------------------------------------------------
#define BB    2
#define QQ    1024
#define HH    32
#define KVH   8
#define HD    64
#define HS    2048
#define K2HS  4096
#define LCK   2
#define SCALE 0.125f

#define NEG_INF (__int_as_float(0xff800000))

// ---------------------------------------------------------------------------
// Scratch (no cudaMalloc allowed)
// ---------------------------------------------------------------------------
__device__ float g_q  [BB * QQ * HH  * HD];
__device__ float g_k  [BB * QQ * KVH * HD];
__device__ float g_v  [BB * QQ * KVH * HD];
__device__ double g_invf[32];

// fp16 operands (single precision except attention Q / P which stay split)
__device__ __half c_hid[2048 * 4096];
__device__ __half c_wq [2048 * 4096];
__device__ __half c_wk [512  * 4096];
__device__ __half c_wv [512  * 4096];
__device__ __half c_wo [2048 * 2048];
__device__ __half c_at [2048 * 2048];
__device__ __half c_qh [2048 * 2048];
__device__ __half c_ql [2048 * 2048];
__device__ __half c_k0 [BB * HH * QQ * HD];
__device__ __half c_v0 [BB * HH * QQ * HD];

// ---------------------------------------------------------------------------
// PTX helpers — plain-sm_100 legal only
// ---------------------------------------------------------------------------
__device__ __forceinline__ uint32_t smem_u32(const void* p) {
    uint32_t a;
    asm("{ .reg .u64 t; cvta.to.shared.u64 t, %1; cvt.u32.u64 %0, t; }"
        : "=r"(a) : "l"(p));
    return a;
}

#define CP_ASYNC16(dst, src) \
    asm volatile("cp.async.cg.shared.global [%0], [%1], 16;" \
                 :: "r"((uint32_t)(dst)), "l"(src))
#define CP_COMMIT() asm volatile("cp.async.commit_group;" ::: "memory")
#define CP_WAIT0()  asm volatile("cp.async.wait_group 0;" ::: "memory")
#define CP_WAIT1()  asm volatile("cp.async.wait_group 1;" ::: "memory")

__device__ __forceinline__ void ldsm4(uint32_t* r, uint32_t addr) {
    asm volatile("ldmatrix.sync.aligned.m8n8.x4.shared.b16 {%0,%1,%2,%3}, [%4];"
        : "=r"(r[0]), "=r"(r[1]), "=r"(r[2]), "=r"(r[3]) : "r"(addr));
}
__device__ __forceinline__ void ldsm4t(uint32_t* r, uint32_t addr) {
    asm volatile("ldmatrix.sync.aligned.m8n8.x4.trans.shared.b16 {%0,%1,%2,%3}, [%4];"
        : "=r"(r[0]), "=r"(r[1]), "=r"(r[2]), "=r"(r[3]) : "r"(addr));
}

__device__ __forceinline__ void mma_tc(float* d, const uint32_t* a, const uint32_t* b) {
    asm volatile(
        "mma.sync.aligned.m16n8k16.row.col.f32.f16.f16.f32 "
        "{%0,%1,%2,%3}, {%4,%5,%6,%7}, {%8,%9}, {%0,%1,%2,%3};"
        : "+f"(d[0]), "+f"(d[1]), "+f"(d[2]), "+f"(d[3])
        : "r"(a[0]), "r"(a[1]), "r"(a[2]), "r"(a[3]), "r"(b[0]), "r"(b[1]));
}

__device__ __forceinline__ uint32_t packhf(float hi, float lo) {
    uint32_t r;
    asm("cvt.rn.f16x2.f32 %0, %1, %2;" : "=r"(r) : "f"(hi), "f"(lo));
    return r;
}

// ---------------------------------------------------------------------------
// inv_freq table setup
// ---------------------------------------------------------------------------
__global__ void setup_invf()
{
    int d = threadIdx.x;
    if (d < 32) g_invf[d] = pow(10000.0, -(double)d / 32.0);
}

// ---------------------------------------------------------------------------
// Batched fp32 -> fp16 single conversion: 7 jobs, one launch.
// Each block = 1024 float4.
// ---------------------------------------------------------------------------
struct BatchJobs {
    const float* x[7];
    __half*      h[7];
    int          start[7];
};

__global__ void convert_batch(BatchJobs jb)
{
    int bid = blockIdx.x;
    int s = 0;
    #pragma unroll
    for (int k = 1; k < 7; k++)
        if (bid >= jb.start[k]) s = k;
    const float4* xp = (const float4*)jb.x[s];
    __half2* hp = (__half2*)jb.h[s];
    int i0 = (bid - jb.start[s]) * 1024 + threadIdx.x;
    float4 v[4];
    #pragma unroll
    for (int u = 0; u < 4; u++)
        v[u] = xp[i0 + u * 256];
    #pragma unroll
    for (int u = 0; u < 4; u++) {
        int i = i0 + u * 256;
        hp[2 * i]     = __halves2half2(__float2half(v[u].x), __float2half(v[u].y));
        hp[2 * i + 1] = __halves2half2(__float2half(v[u].z), __float2half(v[u].w));
    }
}

// ---------------------------------------------------------------------------
// Fused RoPE (+ Q scale + fp16 hi/lo split). k rotated in place (fp32).
// ---------------------------------------------------------------------------
__global__ void rope_conv(float* __restrict__ q, float* __restrict__ k,
                          const int* __restrict__ pos_ids,
                          __half* __restrict__ qh, __half* __restrict__ ql)
{
    const int NQ = BB * QQ * HH  * 32;
    const int NK = BB * QQ * KVH * 32;
    int i = blockIdx.x * blockDim.x + threadIdx.x;
    if (i >= NQ + NK) return;

    const double TWO_PI  = 6.283185307179586476925286766559;
    const double INV_2PI = 0.15915494309189533576888376337251;

    if (i < NQ) {
        int d = i & 31;
        int m = i >> 10;
        size_t off = (size_t)m * (HH * HD) + ((i >> 5) & (HH - 1)) * HD + d;
        double ang = (double)(pos_ids[m] + LCK) * g_invf[d];
        double r = fma(-rint(ang * INV_2PI), TWO_PI, ang);
        float s, c;
        sincosf((float)r, &s, &c);
        float a = q[off], b2 = q[off + 32];
        float r0 = (a * c - b2 * s) * SCALE;
        float r1 = (b2 * c + a * s) * SCALE;
        __half h0 = __float2half(r0);
        __half h1 = __float2half(r1);
        qh[off]      = h0;
        qh[off + 32] = h1;
        ql[off]      = __float2half(r0 - __half2float(h0));
        ql[off + 32] = __float2half(r1 - __half2float(h1));
    } else {
        int j = i - NQ;
        int d = j & 31;
        int m = j >> 8;
        size_t off = (size_t)m * (KVH * HD) + ((j >> 5) & (KVH - 1)) * HD + d;
        double ang = (double)(pos_ids[m] + LCK) * g_invf[d];
        double r = fma(-rint(ang * INV_2PI), TWO_PI, ang);
        float s, c;
        sincosf((float)r, &s, &c);
        float a = k[off], b2 = k[off + 32];
        k[off]      = a  * c - b2 * s;
        k[off + 32] = b2 * c + a  * s;
    }
}

// ---------------------------------------------------------------------------
// Single-product fp16 NT GEMM (128x128, BK=64, 2-stage ring, 2 CTAs/SM).
// Stage = A(128x144) + B(128x144) = 36864B; 2 stages = 73728B.
// ---------------------------------------------------------------------------
#define ROWB   144
#define TILEB  (128 * ROWB)          // 18432
#define STAGEB (2 * TILEB)           // 36864
#define GSMEM_BYTES (2 * STAGEB)     // 73728

__device__ __forceinline__ void load_stage(
    uint32_t sb, int buf, const char* Ah, const char* Bh,
    int bm, int bn, int kb, int K, int tid)
{
    uint32_t st = sb + buf * STAGEB;
    #pragma unroll
    for (int j = 0; j < 8; j++) {
        int c    = tid + 256 * j;           // 0..2047
        int tile = c >> 10;                 // 0..1
        int row  = (c >> 3) & 127;
        int ch   = c & 7;
        const char* base = (tile == 0) ? Ah : Bh;
        int rb = (tile == 0) ? bm : bn;
        uint32_t sa = st + tile * TILEB + row * ROWB + ch * 16;
        const char* ga = base + ((size_t)(rb + row) * K + kb + ch * 8) * 2;
        CP_ASYNC16(sa, ga);
    }
    CP_COMMIT();
}

__global__ __launch_bounds__(256, 2)
void gemm_tc(const __half* __restrict__ Ah_,
             const __half* B0, float* C0, int N0,
             const __half* B1, float* C1, int N1,
             const __half* B2, float* C2, int N2,
             int K)
{
    extern __shared__ __align__(16) char smx[];
    uint32_t sb = smem_u32(smx);
    const int tid  = threadIdx.x;
    const int wid  = tid >> 5;
    const int lane = tid & 31;
    const int wm   = wid >> 1;
    const int wn   = wid & 1;
    const int bm   = blockIdx.y * 128;

    int xt = blockIdx.x;
    const __half* Bh; float* C; int ldc, bn;
    int t0 = N0 >> 7, t1 = N1 >> 7;
    if (xt < t0)           { Bh = B0; C = C0; ldc = N0; bn = xt << 7; }
    else if (xt < t0 + t1) { Bh = B1; C = C1; ldc = N1; bn = (xt - t0) << 7; }
    else                   { Bh = B2; C = C2; ldc = N2; bn = (xt - t0 - t1) << 7; }

    const char* cAh = (const char*)Ah_;
    const char* cBh = (const char*)Bh;

    float acc[2][8][4];
    #pragma unroll
    for (int i = 0; i < 2; i++)
        #pragma unroll
        for (int j = 0; j < 8; j++)
            #pragma unroll
            for (int q = 0; q < 4; q++) acc[i][j][q] = 0.f;

    const int nk = K >> 6;
    load_stage(sb, 0, cAh, cBh, bm, bn, 0,  K, tid);
    load_stage(sb, 1, cAh, cBh, bm, bn, 64, K, tid);

    const int lr = lane & 15;
    const int lc = lane >> 4;

    for (int t = 0; t < nk; t++) {
        CP_WAIT1();
        __syncthreads();
        uint32_t st = sb + (t & 1) * STAGEB;

        #pragma unroll
        for (int k0 = 0; k0 < 64; k0 += 16) {
            uint32_t ah[2][4], bh[4][4];
            uint32_t ao = (uint32_t)((wm * 32 + lr) * ROWB + (k0 + lc * 8) * 2);
            ldsm4(ah[0], st + ao);
            ldsm4(ah[1], st + ao + 16 * ROWB);
            uint32_t bo = (uint32_t)(TILEB + (wn * 64 + lr) * ROWB + (k0 + lc * 8) * 2);
            #pragma unroll
            for (int nt = 0; nt < 4; nt++)
                ldsm4(bh[nt], st + bo + nt * 16 * ROWB);
            #pragma unroll
            for (int mt = 0; mt < 2; mt++) {
                #pragma unroll
                for (int nt = 0; nt < 4; nt++) {
                    uint32_t b0[2] = {bh[nt][0], bh[nt][2]};
                    uint32_t b1[2] = {bh[nt][1], bh[nt][3]};
                    mma_tc(acc[mt][2 * nt],     ah[mt], b0);
                    mma_tc(acc[mt][2 * nt + 1], ah[mt], b1);
                }
            }
        }
        __syncthreads();
        if (t + 2 < nk)
            load_stage(sb, t & 1, cAh, cBh, bm, bn, (t + 2) * 64, K, tid);
        else
            CP_COMMIT();
    }

    const int lg = lane >> 2;
    const int lq = lane & 3;
    #pragma unroll
    for (int mt = 0; mt < 2; mt++) {
        int row = bm + wm * 32 + mt * 16 + lg;
        #pragma unroll
        for (int nf = 0; nf < 8; nf++) {
            float* p = C + (size_t)row * ldc + bn + wn * 64 + nf * 8 + 2 * lq;
            *(float2*)p               = make_float2(acc[mt][nf][0], acc[mt][nf][1]);
            *(float2*)(p + 8 * ldc)   = make_float2(acc[mt][nf][2], acc[mt][nf][3]);
        }
    }
}

// ---------------------------------------------------------------------------
// Tensor-core flash attention, 2-product fp16 (unchanged arithmetic;
// epilogue writes single fp16 output for the single-product Wo GEMM).
// ---------------------------------------------------------------------------
#define BQ    128
#define BKEY  128
#define QROWB 144
#define SM_QH 0
#define SM_QL 18432
#define SM_ST 36864
#define STG_SZ 36864
#define OFF_KH 0
#define OFF_VH 18432
#define ATTN_SMEM2 (SM_ST + 2 * STG_SZ)   // 110592

__device__ __forceinline__ void attn_ldkv(uint32_t sb, int stg,
    const char* kh, const char* vh, size_t base2, int tid)
{
    uint32_t st = sb + SM_ST + stg * STG_SZ;
    #pragma unroll
    for (int j = 0; j < 4; j++) {
        int c = tid + 256 * j;
        int row = c >> 3, ch = c & 7;
        size_t off = base2 + (size_t)row * 128 + ch * 16;
        uint32_t d = row * QROWB + ch * 16;
        CP_ASYNC16(st + OFF_KH + d, kh + off);
        CP_ASYNC16(st + OFF_VH + d, vh + off);
    }
    CP_COMMIT();
}

__global__ __launch_bounds__(256, 1)
void attn_mma(const __half* __restrict__ qh_g, const __half* __restrict__ ql_g,
              const __half* __restrict__ k0, const __half* __restrict__ v0,
              const float* __restrict__ cache_k, const float* __restrict__ cache_v,
              const float* __restrict__ gk, const float* __restrict__ gv,
              __half* __restrict__ outh)
{
    extern __shared__ __align__(16) char smp[];
    uint32_t sb = smem_u32(smp);
    const int tid = threadIdx.x, wid = tid >> 5, lane = tid & 31;
    const int lg = lane >> 2, lq = lane & 3;
    const int qt = (int)gridDim.x - 1 - (int)blockIdx.x;   // LPT
    const int h = blockIdx.y, b = blockIdx.z;
    const int qb = qt * BQ;

    {
        const char* ch_ = (const char*)qh_g;
        const char* cl_ = (const char*)ql_g;
        #pragma unroll
        for (int j = 0; j < 4; j++) {
            int c = tid + 256 * j;
            int row = c >> 3, ch = c & 7;
            size_t off = (((size_t)(b * QQ + qb + row)) * 2048 + h * 64 + ch * 8) * 2;
            uint32_t d = row * QROWB + ch * 16;
            CP_ASYNC16(sb + SM_QH + d, ch_ + off);
            CP_ASYNC16(sb + SM_QL + d, cl_ + off);
        }
        CP_COMMIT();
    }

    const char* ck0 = (const char*)k0;
    const char* cv0 = (const char*)v0;
    size_t kvb2 = ((size_t)(b * HH + h)) * QQ * 64 * 2;
    attn_ldkv(sb, 0, ck0, cv0, kvb2, tid);
    if (qt >= 1)
        attn_ldkv(sb, 1, ck0, cv0, kvb2 + (size_t)BKEY * 128, tid);

    float s[16][4], o[8][4];
    #pragma unroll
    for (int nf = 0; nf < 8; nf++)
        #pragma unroll
        for (int c = 0; c < 4; c++) o[nf][c] = 0.f;
    float mr0 = NEG_INF, mr1 = NEG_INF, lr0 = 0.f, lr1 = 0.f;
    uint32_t qah[4][4], qal[4][4];

    for (int kt = 0; kt <= qt; kt++) {
        if (kt < qt) { CP_WAIT1(); } else { CP_WAIT0(); }
        __syncthreads();
        uint32_t st = sb + SM_ST + (kt & 1) * STG_SZ;

        if (kt == 0) {
            #pragma unroll
            for (int kc = 0; kc < 4; kc++) {
                uint32_t ao = (wid * 16 + (lane & 15)) * QROWB + (kc * 16 + (lane >> 4) * 8) * 2;
                ldsm4(qah[kc], sb + SM_QH + ao);
                ldsm4(qal[kc], sb + SM_QL + ao);
            }
        }

        #pragma unroll
        for (int nf = 0; nf < 16; nf++)
            #pragma unroll
            for (int c = 0; c < 4; c++) s[nf][c] = 0.f;
        #pragma unroll
        for (int kc = 0; kc < 4; kc++) {
            #pragma unroll
            for (int kg = 0; kg < 8; kg++) {
                uint32_t bo = (kg * 16 + (lane & 15)) * QROWB + (kc * 16 + (lane >> 4) * 8) * 2;
                uint32_t bh_[4];
                ldsm4(bh_, st + OFF_KH + bo);
                uint32_t b0[2] = {bh_[0], bh_[2]}, b1[2] = {bh_[1], bh_[3]};
                mma_tc(s[2 * kg],     qah[kc], b0);
                mma_tc(s[2 * kg + 1], qah[kc], b1);
                mma_tc(s[2 * kg],     qal[kc], b0);
                mma_tc(s[2 * kg + 1], qal[kc], b1);
            }
        }

        if (kt == qt) {
            int r0 = wid * 16 + lg;
            #pragma unroll
            for (int nf = 0; nf < 16; nf++) {
                int k0c = nf * 8 + 2 * lq;
                if (k0c     > r0)     s[nf][0] = -1e30f;
                if (k0c + 1 > r0)     s[nf][1] = -1e30f;
                if (k0c     > r0 + 8) s[nf][2] = -1e30f;
                if (k0c + 1 > r0 + 8) s[nf][3] = -1e30f;
            }
        }

        float mx0 = NEG_INF, mx1 = NEG_INF;
        #pragma unroll
        for (int nf = 0; nf < 16; nf++) {
            mx0 = fmaxf(mx0, fmaxf(s[nf][0], s[nf][1]));
            mx1 = fmaxf(mx1, fmaxf(s[nf][2], s[nf][3]));
        }
        mx0 = fmaxf(mx0, __shfl_xor_sync(0xffffffffu, mx0, 1));
        mx0 = fmaxf(mx0, __shfl_xor_sync(0xffffffffu, mx0, 2));
        mx1 = fmaxf(mx1, __shfl_xor_sync(0xffffffffu, mx1, 1));
        mx1 = fmaxf(mx1, __shfl_xor_sync(0xffffffffu, mx1, 2));
        float mn0 = fmaxf(mr0, mx0), mn1 = fmaxf(mr1, mx1);
        float al0 = __expf(mr0 - mn0), al1 = __expf(mr1 - mn1);
        mr0 = mn0; mr1 = mn1;
        float sum0 = 0.f, sum1 = 0.f;
        #pragma unroll
        for (int nf = 0; nf < 16; nf++) {
            s[nf][0] = __expf(s[nf][0] - mn0); sum0 += s[nf][0];
            s[nf][1] = __expf(s[nf][1] - mn0); sum0 += s[nf][1];
            s[nf][2] = __expf(s[nf][2] - mn1); sum1 += s[nf][2];
            s[nf][3] = __expf(s[nf][3] - mn1); sum1 += s[nf][3];
        }
        sum0 += __shfl_xor_sync(0xffffffffu, sum0, 1);
        sum0 += __shfl_xor_sync(0xffffffffu, sum0, 2);
        sum1 += __shfl_xor_sync(0xffffffffu, sum1, 1);
        sum1 += __shfl_xor_sync(0xffffffffu, sum1, 2);
        lr0 = lr0 * al0 + sum0;
        lr1 = lr1 * al1 + sum1;
        #pragma unroll
        for (int nf = 0; nf < 8; nf++) {
            o[nf][0] *= al0; o[nf][1] *= al0; o[nf][2] *= al1; o[nf][3] *= al1;
        }

        #pragma unroll
        for (int kc2 = 0; kc2 < 8; kc2++) {
            uint32_t pah[4], pal[4];
            #pragma unroll
            for (int t2 = 0; t2 < 2; t2++) {
                float* sv = s[2 * kc2 + t2];
                __half h0 = __float2half(sv[0]);
                __half h1 = __float2half(sv[1]);
                __half h2 = __float2half(sv[2]);
                __half h3 = __float2half(sv[3]);
                pah[2 * t2]     = ((uint32_t)__half_as_ushort(h1) << 16) | __half_as_ushort(h0);
                pah[2 * t2 + 1] = ((uint32_t)__half_as_ushort(h3) << 16) | __half_as_ushort(h2);
                pal[2 * t2]     = packhf(sv[1] - __half2float(h1), sv[0] - __half2float(h0));
                pal[2 * t2 + 1] = packhf(sv[3] - __half2float(h3), sv[2] - __half2float(h2));
            }
            #pragma unroll
            for (int dg = 0; dg < 4; dg++) {
                uint32_t vo = (kc2 * 16 + (lane & 15)) * QROWB + dg * 32 + (lane >> 4) * 16;
                uint32_t vh_[4];
                ldsm4t(vh_, st + OFF_VH + vo);
                uint32_t b0[2] = {vh_[0], vh_[1]}, b1[2] = {vh_[2], vh_[3]};
                mma_tc(o[2 * dg],     pah, b0);
                mma_tc(o[2 * dg + 1], pah, b1);
                mma_tc(o[2 * dg],     pal, b0);
                mma_tc(o[2 * dg + 1], pal, b1);
            }
        }
        __syncthreads();
        if (kt + 2 <= qt)
            attn_ldkv(sb, kt & 1, ck0, cv0,
                      kvb2 + (size_t)(kt + 2) * BKEY * 128, tid);
    }

    // ---- two diagonal tail keys per row ----
    #pragma unroll 1
    for (int e = 0; e < 2; e++) {
        const float* tk; const float* tv; int stride;
        if (e == 0) {
            size_t off = (((size_t)BB + b) * HH + h) * QQ * HD + (size_t)qb * HD;
            tk = cache_k + off; tv = cache_v + off; stride = 64;
        } else {
            size_t off = ((size_t)(b * QQ + qb)) * 512 + (h >> 2) * 64;
            tk = gk + off; tv = gv + off; stride = 512;
        }
        #pragma unroll
        for (int half = 0; half < 2; half++) {
            int rl = wid * 16 + lg + half * 8;
            const __half* qhp = (const __half*)(smp + SM_QH + rl * QROWB);
            const __half* qlp = (const __half*)(smp + SM_QL + rl * QROWB);
            float dot = 0.f;
            #pragma unroll
            for (int dd = 0; dd < 16; dd++) {
                int d = lq * 16 + dd;
                float qv = __half2float(qhp[d]) + __half2float(qlp[d]);
                dot += qv * tk[(size_t)rl * stride + d];
            }
            dot += __shfl_xor_sync(0xffffffffu, dot, 1);
            dot += __shfl_xor_sync(0xffffffffu, dot, 2);
            float mo = half ? mr1 : mr0;
            float mn = fmaxf(mo, dot);
            float a = __expf(mo - mn), p = __expf(dot - mn);
            if (half) { mr1 = mn; lr1 = lr1 * a + p; }
            else      { mr0 = mn; lr0 = lr0 * a + p; }
            #pragma unroll
            for (int nf = 0; nf < 8; nf++) {
                int d0 = nf * 8 + 2 * lq;
                float v0_ = tv[(size_t)rl * stride + d0];
                float v1_ = tv[(size_t)rl * stride + d0 + 1];
                o[nf][2 * half]     = o[nf][2 * half]     * a + p * v0_;
                o[nf][2 * half + 1] = o[nf][2 * half + 1] * a + p * v1_;
            }
        }
    }

    float inv0 = 1.f / lr0, inv1 = 1.f / lr1;
    #pragma unroll
    for (int half = 0; half < 2; half++) {
        int qrow = qb + wid * 16 + lg + half * 8;
        float inv = half ? inv1 : inv0;
        size_t base = ((size_t)(b * QQ) + qrow) * 2048 + h * 64;
        #pragma unroll
        for (int nf = 0; nf < 8; nf++) {
            float x0 = o[nf][2 * half] * inv;
            float x1 = o[nf][2 * half + 1] * inv;
            *(__half2*)(outh + base + nf * 8 + 2 * lq) =
                __halves2half2(__float2half(x0), __float2half(x1));
        }
    }
}

// ---------------------------------------------------------------------------
// Launch
// ---------------------------------------------------------------------------
extern "C" void kernel_launch(void* const* d_in, const int* in_sizes, int n_in,
                              void* d_out, int out_size)
{
    (void)in_sizes; (void)n_in; (void)out_size;

    const float* hidden = (const float*)d_in[0];
    const float* Wq     = (const float*)d_in[1];
    const float* Wk     = (const float*)d_in[2];
    const float* Wv     = (const float*)d_in[3];
    const float* Wo     = (const float*)d_in[4];
    const float* ck     = (const float*)d_in[5];
    const float* cv     = (const float*)d_in[6];
    const int*   pos    = (const int*)d_in[8];
    float* out = (float*)d_out;

    float *gq, *gk, *gv;
    cudaGetSymbolAddress((void**)&gq, g_q);
    cudaGetSymbolAddress((void**)&gk, g_k);
    cudaGetSymbolAddress((void**)&gv, g_v);

    __half *hid, *wq, *wk, *wv, *wo, *at, *qh, *ql, *k0, *v0;
    cudaGetSymbolAddress((void**)&hid, c_hid);
    cudaGetSymbolAddress((void**)&wq,  c_wq);
    cudaGetSymbolAddress((void**)&wk,  c_wk);
    cudaGetSymbolAddress((void**)&wv,  c_wv);
    cudaGetSymbolAddress((void**)&wo,  c_wo);
    cudaGetSymbolAddress((void**)&at,  c_at);
    cudaGetSymbolAddress((void**)&qh,  c_qh);
    cudaGetSymbolAddress((void**)&ql,  c_ql);
    cudaGetSymbolAddress((void**)&k0,  c_k0);
    cudaGetSymbolAddress((void**)&v0,  c_v0);

    cudaFuncSetAttribute(gemm_tc,
                         cudaFuncAttributeMaxDynamicSharedMemorySize, GSMEM_BYTES);
    cudaFuncSetAttribute(attn_mma,
                         cudaFuncAttributeMaxDynamicSharedMemorySize, ATTN_SMEM2);

    const int M = BB * QQ;   // 2048

    setup_invf<<<1, 32>>>();

    // all fp32 -> fp16 conversions in ONE batched launch (7 jobs)
    {
        BatchJobs jb;
        jb.x[0] = hidden; jb.h[0] = hid;  // 2048*4096 -> 2048 blocks
        jb.x[1] = Wq;     jb.h[1] = wq;   // 2048*4096 -> 2048
        jb.x[2] = Wk;     jb.h[2] = wk;   //  512*4096 ->  512
        jb.x[3] = Wv;     jb.h[3] = wv;   //  512*4096 ->  512
        jb.x[4] = Wo;     jb.h[4] = wo;   // 2048*2048 -> 1024
        jb.x[5] = ck;     jb.h[5] = k0;   // 4M        -> 1024
        jb.x[6] = cv;     jb.h[6] = v0;   // 4M        -> 1024
        jb.start[0] = 0;    jb.start[1] = 2048; jb.start[2] = 4096;
        jb.start[3] = 4608; jb.start[4] = 5120; jb.start[5] = 6144;
        jb.start[6] = 7168;
        convert_batch<<<8192, 256>>>(jb);
    }

    // fused QKV projection (single-product fp16)
    gemm_tc<<<dim3(24, M / 128), 256, GSMEM_BYTES>>>(
        hid,
        wq, gq, HH * HD,
        wk, gk, KVH * HD,
        wv, gv, KVH * HD,
        K2HS);

    // fused RoPE + Q split (attention stays 2-product)
    {
        int total = BB * QQ * (HH + KVH) * 32;
        rope_conv<<<(total + 255) / 256, 256>>>(gq, gk, pos, qh, ql);
    }

    attn_mma<<<dim3(QQ / BQ, HH, BB), 256, ATTN_SMEM2>>>(
        qh, ql, k0, v0, ck, cv, gk, gv, at);

    // output projection (single-product fp16)
    gemm_tc<<<dim3(16, M / 128), 256, GSMEM_BYTES>>>(
        at,
        wo, out, HS,
        (const __half*)0, (float*)0, 0,
        (const __half*)0, (float*)0, 0,
        HH * HD);
}

// round 17
// speedup vs baseline: 1.7394x; 1.0542x over previous
#include <cuda_runtime.h>
#include <cuda_fp16.h>
#include <math.h>
#include <stdint.h>

// ---------------------------------------------------------------------------
// Problem constants
// ---------------------------------------------------------------------------
#define BB    2
#define QQ    1024
#define HH    32
#define KVH   8
#define HD    64
#define HS    2048
#define K2HS  4096
#define LCK   2
#define SCALE 0.125f

#define NEG_INF (__int_as_float(0xff800000))

// ---------------------------------------------------------------------------
// Scratch (no cudaMalloc allowed)
// ---------------------------------------------------------------------------
__device__ float g_q  [BB * QQ * HH  * HD];
__device__ float g_k  [BB * QQ * KVH * HD];
__device__ float g_v  [BB * QQ * KVH * HD];
__device__ double g_invf[32];

// fp16 operands (all single precision now)
__device__ __half c_hid[2048 * 4096];
__device__ __half c_wq [2048 * 4096];
__device__ __half c_wk [512  * 4096];
__device__ __half c_wv [512  * 4096];
__device__ __half c_wo [2048 * 2048];
__device__ __half c_at [2048 * 2048];
__device__ __half c_qh [2048 * 2048];
__device__ __half c_k0 [BB * HH * QQ * HD];
__device__ __half c_v0 [BB * HH * QQ * HD];

// ---------------------------------------------------------------------------
// PTX helpers — plain-sm_100 legal only
// ---------------------------------------------------------------------------
__device__ __forceinline__ uint32_t smem_u32(const void* p) {
    uint32_t a;
    asm("{ .reg .u64 t; cvta.to.shared.u64 t, %1; cvt.u32.u64 %0, t; }"
        : "=r"(a) : "l"(p));
    return a;
}

#define CP_ASYNC16(dst, src) \
    asm volatile("cp.async.cg.shared.global [%0], [%1], 16;" \
                 :: "r"((uint32_t)(dst)), "l"(src))
#define CP_COMMIT() asm volatile("cp.async.commit_group;" ::: "memory")
#define CP_WAIT0()  asm volatile("cp.async.wait_group 0;" ::: "memory")
#define CP_WAIT1()  asm volatile("cp.async.wait_group 1;" ::: "memory")

__device__ __forceinline__ void ldsm4(uint32_t* r, uint32_t addr) {
    asm volatile("ldmatrix.sync.aligned.m8n8.x4.shared.b16 {%0,%1,%2,%3}, [%4];"
        : "=r"(r[0]), "=r"(r[1]), "=r"(r[2]), "=r"(r[3]) : "r"(addr));
}
__device__ __forceinline__ void ldsm4t(uint32_t* r, uint32_t addr) {
    asm volatile("ldmatrix.sync.aligned.m8n8.x4.trans.shared.b16 {%0,%1,%2,%3}, [%4];"
        : "=r"(r[0]), "=r"(r[1]), "=r"(r[2]), "=r"(r[3]) : "r"(addr));
}

__device__ __forceinline__ void mma_tc(float* d, const uint32_t* a, const uint32_t* b) {
    asm volatile(
        "mma.sync.aligned.m16n8k16.row.col.f32.f16.f16.f32 "
        "{%0,%1,%2,%3}, {%4,%5,%6,%7}, {%8,%9}, {%0,%1,%2,%3};"
        : "+f"(d[0]), "+f"(d[1]), "+f"(d[2]), "+f"(d[3])
        : "r"(a[0]), "r"(a[1]), "r"(a[2]), "r"(a[3]), "r"(b[0]), "r"(b[1]));
}

// ---------------------------------------------------------------------------
// inv_freq table setup
// ---------------------------------------------------------------------------
__global__ void setup_invf()
{
    int d = threadIdx.x;
    if (d < 32) g_invf[d] = pow(10000.0, -(double)d / 32.0);
}

// ---------------------------------------------------------------------------
// Batched fp32 -> fp16 single conversion: 7 jobs, one launch.
// ---------------------------------------------------------------------------
struct BatchJobs {
    const float* x[7];
    __half*      h[7];
    int          start[7];
};

__global__ void convert_batch(BatchJobs jb)
{
    int bid = blockIdx.x;
    int s = 0;
    #pragma unroll
    for (int k = 1; k < 7; k++)
        if (bid >= jb.start[k]) s = k;
    const float4* xp = (const float4*)jb.x[s];
    __half2* hp = (__half2*)jb.h[s];
    int i0 = (bid - jb.start[s]) * 1024 + threadIdx.x;
    float4 v[4];
    #pragma unroll
    for (int u = 0; u < 4; u++)
        v[u] = xp[i0 + u * 256];
    #pragma unroll
    for (int u = 0; u < 4; u++) {
        int i = i0 + u * 256;
        hp[2 * i]     = __halves2half2(__float2half(v[u].x), __float2half(v[u].y));
        hp[2 * i + 1] = __halves2half2(__float2half(v[u].z), __float2half(v[u].w));
    }
}

// ---------------------------------------------------------------------------
// Fused RoPE (+ Q scale + fp16 convert). k rotated in place (fp32).
// ---------------------------------------------------------------------------
__global__ void rope_conv(float* __restrict__ q, float* __restrict__ k,
                          const int* __restrict__ pos_ids,
                          __half* __restrict__ qh)
{
    const int NQ = BB * QQ * HH  * 32;
    const int NK = BB * QQ * KVH * 32;
    int i = blockIdx.x * blockDim.x + threadIdx.x;
    if (i >= NQ + NK) return;

    const double TWO_PI  = 6.283185307179586476925286766559;
    const double INV_2PI = 0.15915494309189533576888376337251;

    if (i < NQ) {
        int d = i & 31;
        int m = i >> 10;
        size_t off = (size_t)m * (HH * HD) + ((i >> 5) & (HH - 1)) * HD + d;
        double ang = (double)(pos_ids[m] + LCK) * g_invf[d];
        double r = fma(-rint(ang * INV_2PI), TWO_PI, ang);
        float s, c;
        sincosf((float)r, &s, &c);
        float a = q[off], b2 = q[off + 32];
        qh[off]      = __float2half((a * c - b2 * s) * SCALE);
        qh[off + 32] = __float2half((b2 * c + a * s) * SCALE);
    } else {
        int j = i - NQ;
        int d = j & 31;
        int m = j >> 8;
        size_t off = (size_t)m * (KVH * HD) + ((j >> 5) & (KVH - 1)) * HD + d;
        double ang = (double)(pos_ids[m] + LCK) * g_invf[d];
        double r = fma(-rint(ang * INV_2PI), TWO_PI, ang);
        float s, c;
        sincosf((float)r, &s, &c);
        float a = k[off], b2 = k[off + 32];
        k[off]      = a  * c - b2 * s;
        k[off + 32] = b2 * c + a  * s;
    }
}

// ---------------------------------------------------------------------------
// Single-product fp16 NT GEMM (128x128, BK=64, 2-stage ring, 2 CTAs/SM) —
// byte-identical to round-16 winner.
// ---------------------------------------------------------------------------
#define ROWB   144
#define TILEB  (128 * ROWB)          // 18432
#define STAGEB (2 * TILEB)           // 36864
#define GSMEM_BYTES (2 * STAGEB)     // 73728

__device__ __forceinline__ void load_stage(
    uint32_t sb, int buf, const char* Ah, const char* Bh,
    int bm, int bn, int kb, int K, int tid)
{
    uint32_t st = sb + buf * STAGEB;
    #pragma unroll
    for (int j = 0; j < 8; j++) {
        int c    = tid + 256 * j;           // 0..2047
        int tile = c >> 10;                 // 0..1
        int row  = (c >> 3) & 127;
        int ch   = c & 7;
        const char* base = (tile == 0) ? Ah : Bh;
        int rb = (tile == 0) ? bm : bn;
        uint32_t sa = st + tile * TILEB + row * ROWB + ch * 16;
        const char* ga = base + ((size_t)(rb + row) * K + kb + ch * 8) * 2;
        CP_ASYNC16(sa, ga);
    }
    CP_COMMIT();
}

__global__ __launch_bounds__(256, 2)
void gemm_tc(const __half* __restrict__ Ah_,
             const __half* B0, float* C0, int N0,
             const __half* B1, float* C1, int N1,
             const __half* B2, float* C2, int N2,
             int K)
{
    extern __shared__ __align__(16) char smx[];
    uint32_t sb = smem_u32(smx);
    const int tid  = threadIdx.x;
    const int wid  = tid >> 5;
    const int lane = tid & 31;
    const int wm   = wid >> 1;
    const int wn   = wid & 1;
    const int bm   = blockIdx.y * 128;

    int xt = blockIdx.x;
    const __half* Bh; float* C; int ldc, bn;
    int t0 = N0 >> 7, t1 = N1 >> 7;
    if (xt < t0)           { Bh = B0; C = C0; ldc = N0; bn = xt << 7; }
    else if (xt < t0 + t1) { Bh = B1; C = C1; ldc = N1; bn = (xt - t0) << 7; }
    else                   { Bh = B2; C = C2; ldc = N2; bn = (xt - t0 - t1) << 7; }

    const char* cAh = (const char*)Ah_;
    const char* cBh = (const char*)Bh;

    float acc[2][8][4];
    #pragma unroll
    for (int i = 0; i < 2; i++)
        #pragma unroll
        for (int j = 0; j < 8; j++)
            #pragma unroll
            for (int q = 0; q < 4; q++) acc[i][j][q] = 0.f;

    const int nk = K >> 6;
    load_stage(sb, 0, cAh, cBh, bm, bn, 0,  K, tid);
    load_stage(sb, 1, cAh, cBh, bm, bn, 64, K, tid);

    const int lr = lane & 15;
    const int lc = lane >> 4;

    for (int t = 0; t < nk; t++) {
        CP_WAIT1();
        __syncthreads();
        uint32_t st = sb + (t & 1) * STAGEB;

        #pragma unroll
        for (int k0 = 0; k0 < 64; k0 += 16) {
            uint32_t ah[2][4], bh[4][4];
            uint32_t ao = (uint32_t)((wm * 32 + lr) * ROWB + (k0 + lc * 8) * 2);
            ldsm4(ah[0], st + ao);
            ldsm4(ah[1], st + ao + 16 * ROWB);
            uint32_t bo = (uint32_t)(TILEB + (wn * 64 + lr) * ROWB + (k0 + lc * 8) * 2);
            #pragma unroll
            for (int nt = 0; nt < 4; nt++)
                ldsm4(bh[nt], st + bo + nt * 16 * ROWB);
            #pragma unroll
            for (int mt = 0; mt < 2; mt++) {
                #pragma unroll
                for (int nt = 0; nt < 4; nt++) {
                    uint32_t b0[2] = {bh[nt][0], bh[nt][2]};
                    uint32_t b1[2] = {bh[nt][1], bh[nt][3]};
                    mma_tc(acc[mt][2 * nt],     ah[mt], b0);
                    mma_tc(acc[mt][2 * nt + 1], ah[mt], b1);
                }
            }
        }
        __syncthreads();
        if (t + 2 < nk)
            load_stage(sb, t & 1, cAh, cBh, bm, bn, (t + 2) * 64, K, tid);
        else
            CP_COMMIT();
    }

    const int lg = lane >> 2;
    const int lq = lane & 3;
    #pragma unroll
    for (int mt = 0; mt < 2; mt++) {
        int row = bm + wm * 32 + mt * 16 + lg;
        #pragma unroll
        for (int nf = 0; nf < 8; nf++) {
            float* p = C + (size_t)row * ldc + bn + wn * 64 + nf * 8 + 2 * lq;
            *(float2*)p               = make_float2(acc[mt][nf][0], acc[mt][nf][1]);
            *(float2*)(p + 8 * ldc)   = make_float2(acc[mt][nf][2], acc[mt][nf][3]);
        }
    }
}

// ---------------------------------------------------------------------------
// Tensor-core flash attention, single-product fp16.
// Q single fp16 (smem 18432B), K/V single fp16 stages.
// ---------------------------------------------------------------------------
#define BQ    128
#define BKEY  128
#define QROWB 144
#define SM_QH 0
#define SM_ST 18432
#define STG_SZ 36864
#define OFF_KH 0
#define OFF_VH 18432
#define ATTN_SMEM2 (SM_ST + 2 * STG_SZ)   // 92160

__device__ __forceinline__ void attn_ldkv(uint32_t sb, int stg,
    const char* kh, const char* vh, size_t base2, int tid)
{
    uint32_t st = sb + SM_ST + stg * STG_SZ;
    #pragma unroll
    for (int j = 0; j < 4; j++) {
        int c = tid + 256 * j;
        int row = c >> 3, ch = c & 7;
        size_t off = base2 + (size_t)row * 128 + ch * 16;
        uint32_t d = row * QROWB + ch * 16;
        CP_ASYNC16(st + OFF_KH + d, kh + off);
        CP_ASYNC16(st + OFF_VH + d, vh + off);
    }
    CP_COMMIT();
}

__global__ __launch_bounds__(256, 1)
void attn_mma(const __half* __restrict__ qh_g,
              const __half* __restrict__ k0, const __half* __restrict__ v0,
              const float* __restrict__ cache_k, const float* __restrict__ cache_v,
              const float* __restrict__ gk, const float* __restrict__ gv,
              __half* __restrict__ outh)
{
    extern __shared__ __align__(16) char smp[];
    uint32_t sb = smem_u32(smp);
    const int tid = threadIdx.x, wid = tid >> 5, lane = tid & 31;
    const int lg = lane >> 2, lq = lane & 3;
    const int qt = (int)gridDim.x - 1 - (int)blockIdx.x;   // LPT
    const int h = blockIdx.y, b = blockIdx.z;
    const int qb = qt * BQ;

    // Q tile load (single fp16: 128 rows x 128 bytes = 1024 16B chunks)
    {
        const char* ch_ = (const char*)qh_g;
        #pragma unroll
        for (int j = 0; j < 4; j++) {
            int c = tid + 256 * j;
            int row = c >> 3, ch = c & 7;
            size_t off = (((size_t)(b * QQ + qb + row)) * 2048 + h * 64 + ch * 8) * 2;
            CP_ASYNC16(sb + SM_QH + row * QROWB + ch * 16, ch_ + off);
        }
        CP_COMMIT();
    }

    const char* ck0 = (const char*)k0;
    const char* cv0 = (const char*)v0;
    size_t kvb2 = ((size_t)(b * HH + h)) * QQ * 64 * 2;
    attn_ldkv(sb, 0, ck0, cv0, kvb2, tid);
    if (qt >= 1)
        attn_ldkv(sb, 1, ck0, cv0, kvb2 + (size_t)BKEY * 128, tid);

    float s[16][4], o[8][4];
    #pragma unroll
    for (int nf = 0; nf < 8; nf++)
        #pragma unroll
        for (int c = 0; c < 4; c++) o[nf][c] = 0.f;
    float mr0 = NEG_INF, mr1 = NEG_INF, lr0 = 0.f, lr1 = 0.f;
    uint32_t qah[4][4];

    for (int kt = 0; kt <= qt; kt++) {
        if (kt < qt) { CP_WAIT1(); } else { CP_WAIT0(); }
        __syncthreads();
        uint32_t st = sb + SM_ST + (kt & 1) * STG_SZ;

        if (kt == 0) {
            #pragma unroll
            for (int kc = 0; kc < 4; kc++) {
                uint32_t ao = (wid * 16 + (lane & 15)) * QROWB + (kc * 16 + (lane >> 4) * 8) * 2;
                ldsm4(qah[kc], sb + SM_QH + ao);
            }
        }

        #pragma unroll
        for (int nf = 0; nf < 16; nf++)
            #pragma unroll
            for (int c = 0; c < 4; c++) s[nf][c] = 0.f;
        #pragma unroll
        for (int kc = 0; kc < 4; kc++) {
            #pragma unroll
            for (int kg = 0; kg < 8; kg++) {
                uint32_t bo = (kg * 16 + (lane & 15)) * QROWB + (kc * 16 + (lane >> 4) * 8) * 2;
                uint32_t bh_[4];
                ldsm4(bh_, st + OFF_KH + bo);
                uint32_t b0[2] = {bh_[0], bh_[2]}, b1[2] = {bh_[1], bh_[3]};
                mma_tc(s[2 * kg],     qah[kc], b0);
                mma_tc(s[2 * kg + 1], qah[kc], b1);
            }
        }

        if (kt == qt) {
            int r0 = wid * 16 + lg;
            #pragma unroll
            for (int nf = 0; nf < 16; nf++) {
                int k0c = nf * 8 + 2 * lq;
                if (k0c     > r0)     s[nf][0] = -1e30f;
                if (k0c + 1 > r0)     s[nf][1] = -1e30f;
                if (k0c     > r0 + 8) s[nf][2] = -1e30f;
                if (k0c + 1 > r0 + 8) s[nf][3] = -1e30f;
            }
        }

        float mx0 = NEG_INF, mx1 = NEG_INF;
        #pragma unroll
        for (int nf = 0; nf < 16; nf++) {
            mx0 = fmaxf(mx0, fmaxf(s[nf][0], s[nf][1]));
            mx1 = fmaxf(mx1, fmaxf(s[nf][2], s[nf][3]));
        }
        mx0 = fmaxf(mx0, __shfl_xor_sync(0xffffffffu, mx0, 1));
        mx0 = fmaxf(mx0, __shfl_xor_sync(0xffffffffu, mx0, 2));
        mx1 = fmaxf(mx1, __shfl_xor_sync(0xffffffffu, mx1, 1));
        mx1 = fmaxf(mx1, __shfl_xor_sync(0xffffffffu, mx1, 2));
        float mn0 = fmaxf(mr0, mx0), mn1 = fmaxf(mr1, mx1);
        float al0 = __expf(mr0 - mn0), al1 = __expf(mr1 - mn1);
        mr0 = mn0; mr1 = mn1;
        float sum0 = 0.f, sum1 = 0.f;
        #pragma unroll
        for (int nf = 0; nf < 16; nf++) {
            s[nf][0] = __expf(s[nf][0] - mn0); sum0 += s[nf][0];
            s[nf][1] = __expf(s[nf][1] - mn0); sum0 += s[nf][1];
            s[nf][2] = __expf(s[nf][2] - mn1); sum1 += s[nf][2];
            s[nf][3] = __expf(s[nf][3] - mn1); sum1 += s[nf][3];
        }
        sum0 += __shfl_xor_sync(0xffffffffu, sum0, 1);
        sum0 += __shfl_xor_sync(0xffffffffu, sum0, 2);
        sum1 += __shfl_xor_sync(0xffffffffu, sum1, 1);
        sum1 += __shfl_xor_sync(0xffffffffu, sum1, 2);
        lr0 = lr0 * al0 + sum0;
        lr1 = lr1 * al1 + sum1;
        #pragma unroll
        for (int nf = 0; nf < 8; nf++) {
            o[nf][0] *= al0; o[nf][1] *= al0; o[nf][2] *= al1; o[nf][3] *= al1;
        }

        #pragma unroll
        for (int kc2 = 0; kc2 < 8; kc2++) {
            uint32_t pah[4];
            #pragma unroll
            for (int t2 = 0; t2 < 2; t2++) {
                float* sv = s[2 * kc2 + t2];
                __half h0 = __float2half(sv[0]);
                __half h1 = __float2half(sv[1]);
                __half h2 = __float2half(sv[2]);
                __half h3 = __float2half(sv[3]);
                pah[2 * t2]     = ((uint32_t)__half_as_ushort(h1) << 16) | __half_as_ushort(h0);
                pah[2 * t2 + 1] = ((uint32_t)__half_as_ushort(h3) << 16) | __half_as_ushort(h2);
            }
            #pragma unroll
            for (int dg = 0; dg < 4; dg++) {
                uint32_t vo = (kc2 * 16 + (lane & 15)) * QROWB + dg * 32 + (lane >> 4) * 16;
                uint32_t vh_[4];
                ldsm4t(vh_, st + OFF_VH + vo);
                uint32_t b0[2] = {vh_[0], vh_[1]}, b1[2] = {vh_[2], vh_[3]};
                mma_tc(o[2 * dg],     pah, b0);
                mma_tc(o[2 * dg + 1], pah, b1);
            }
        }
        __syncthreads();
        if (kt + 2 <= qt)
            attn_ldkv(sb, kt & 1, ck0, cv0,
                      kvb2 + (size_t)(kt + 2) * BKEY * 128, tid);
    }

    // ---- two diagonal tail keys per row ----
    #pragma unroll 1
    for (int e = 0; e < 2; e++) {
        const float* tk; const float* tv; int stride;
        if (e == 0) {
            size_t off = (((size_t)BB + b) * HH + h) * QQ * HD + (size_t)qb * HD;
            tk = cache_k + off; tv = cache_v + off; stride = 64;
        } else {
            size_t off = ((size_t)(b * QQ + qb)) * 512 + (h >> 2) * 64;
            tk = gk + off; tv = gv + off; stride = 512;
        }
        #pragma unroll
        for (int half = 0; half < 2; half++) {
            int rl = wid * 16 + lg + half * 8;
            const __half* qhp = (const __half*)(smp + SM_QH + rl * QROWB);
            float dot = 0.f;
            #pragma unroll
            for (int dd = 0; dd < 16; dd++) {
                int d = lq * 16 + dd;
                dot += __half2float(qhp[d]) * tk[(size_t)rl * stride + d];
            }
            dot += __shfl_xor_sync(0xffffffffu, dot, 1);
            dot += __shfl_xor_sync(0xffffffffu, dot, 2);
            float mo = half ? mr1 : mr0;
            float mn = fmaxf(mo, dot);
            float a = __expf(mo - mn), p = __expf(dot - mn);
            if (half) { mr1 = mn; lr1 = lr1 * a + p; }
            else      { mr0 = mn; lr0 = lr0 * a + p; }
            #pragma unroll
            for (int nf = 0; nf < 8; nf++) {
                int d0 = nf * 8 + 2 * lq;
                float v0_ = tv[(size_t)rl * stride + d0];
                float v1_ = tv[(size_t)rl * stride + d0 + 1];
                o[nf][2 * half]     = o[nf][2 * half]     * a + p * v0_;
                o[nf][2 * half + 1] = o[nf][2 * half + 1] * a + p * v1_;
            }
        }
    }

    float inv0 = 1.f / lr0, inv1 = 1.f / lr1;
    #pragma unroll
    for (int half = 0; half < 2; half++) {
        int qrow = qb + wid * 16 + lg + half * 8;
        float inv = half ? inv1 : inv0;
        size_t base = ((size_t)(b * QQ) + qrow) * 2048 + h * 64;
        #pragma unroll
        for (int nf = 0; nf < 8; nf++) {
            float x0 = o[nf][2 * half] * inv;
            float x1 = o[nf][2 * half + 1] * inv;
            *(__half2*)(outh + base + nf * 8 + 2 * lq) =
                __halves2half2(__float2half(x0), __float2half(x1));
        }
    }
}

// ---------------------------------------------------------------------------
// Launch
// ---------------------------------------------------------------------------
extern "C" void kernel_launch(void* const* d_in, const int* in_sizes, int n_in,
                              void* d_out, int out_size)
{
    (void)in_sizes; (void)n_in; (void)out_size;

    const float* hidden = (const float*)d_in[0];
    const float* Wq     = (const float*)d_in[1];
    const float* Wk     = (const float*)d_in[2];
    const float* Wv     = (const float*)d_in[3];
    const float* Wo     = (const float*)d_in[4];
    const float* ck     = (const float*)d_in[5];
    const float* cv     = (const float*)d_in[6];
    const int*   pos    = (const int*)d_in[8];
    float* out = (float*)d_out;

    float *gq, *gk, *gv;
    cudaGetSymbolAddress((void**)&gq, g_q);
    cudaGetSymbolAddress((void**)&gk, g_k);
    cudaGetSymbolAddress((void**)&gv, g_v);

    __half *hid, *wq, *wk, *wv, *wo, *at, *qh, *k0, *v0;
    cudaGetSymbolAddress((void**)&hid, c_hid);
    cudaGetSymbolAddress((void**)&wq,  c_wq);
    cudaGetSymbolAddress((void**)&wk,  c_wk);
    cudaGetSymbolAddress((void**)&wv,  c_wv);
    cudaGetSymbolAddress((void**)&wo,  c_wo);
    cudaGetSymbolAddress((void**)&at,  c_at);
    cudaGetSymbolAddress((void**)&qh,  c_qh);
    cudaGetSymbolAddress((void**)&k0,  c_k0);
    cudaGetSymbolAddress((void**)&v0,  c_v0);

    cudaFuncSetAttribute(gemm_tc,
                         cudaFuncAttributeMaxDynamicSharedMemorySize, GSMEM_BYTES);
    cudaFuncSetAttribute(attn_mma,
                         cudaFuncAttributeMaxDynamicSharedMemorySize, ATTN_SMEM2);

    const int M = BB * QQ;   // 2048

    setup_invf<<<1, 32>>>();

    // all fp32 -> fp16 conversions in ONE batched launch (7 jobs)
    {
        BatchJobs jb;
        jb.x[0] = hidden; jb.h[0] = hid;
        jb.x[1] = Wq;     jb.h[1] = wq;
        jb.x[2] = Wk;     jb.h[2] = wk;
        jb.x[3] = Wv;     jb.h[3] = wv;
        jb.x[4] = Wo;     jb.h[4] = wo;
        jb.x[5] = ck;     jb.h[5] = k0;
        jb.x[6] = cv;     jb.h[6] = v0;
        jb.start[0] = 0;    jb.start[1] = 2048; jb.start[2] = 4096;
        jb.start[3] = 4608; jb.start[4] = 5120; jb.start[5] = 6144;
        jb.start[6] = 7168;
        convert_batch<<<8192, 256>>>(jb);
    }

    // fused QKV projection (single-product fp16)
    gemm_tc<<<dim3(24, M / 128), 256, GSMEM_BYTES>>>(
        hid,
        wq, gq, HH * HD,
        wk, gk, KVH * HD,
        wv, gv, KVH * HD,
        K2HS);

    // fused RoPE + Q convert (single fp16)
    {
        int total = BB * QQ * (HH + KVH) * 32;
        rope_conv<<<(total + 255) / 256, 256>>>(gq, gk, pos, qh);
    }

    attn_mma<<<dim3(QQ / BQ, HH, BB), 256, ATTN_SMEM2>>>(
        qh, k0, v0, ck, cv, gk, gv, at);

    // output projection (single-product fp16)
    gemm_tc<<<dim3(16, M / 128), 256, GSMEM_BYTES>>>(
        at,
        wo, out, HS,
        (const __half*)0, (float*)0, 0,
        (const __half*)0, (float*)0, 0,
        HH * HD);
}